// round 3
// baseline (speedup 1.0000x reference)
#include <cuda_runtime.h>
#include <math.h>

#define N_NODES 100000
#define SEQ 16

// Scratch activations (device globals: no allocation allowed).
__device__ float g_h0[N_NODES * 16];
__device__ float g_h1[N_NODES * 32];
__device__ float g_h2[N_NODES * 64];
__device__ float g_h3[N_NODES * 128];
__device__ float g_h4[N_NODES * 256];
__device__ int   g_idx[N_NODES * SEQ];
__device__ int   g_is64;

__device__ __forceinline__ float elu(float v) {
    return v > 0.f ? v : expm1f(v);
}

// Packed f32x2 helpers (Blackwell FFMA2 — only reachable via PTX).
__device__ __forceinline__ void ffma2(unsigned long long& d,
                                      unsigned long long a,
                                      unsigned long long b) {
    asm("fma.rn.f32x2 %0, %1, %2, %0;" : "+l"(d) : "l"(a), "l"(b));
}
__device__ __forceinline__ unsigned long long dup2(float x) {
    unsigned long long r;
    asm("mov.b64 %0, {%1, %1};" : "=l"(r) : "f"(x));
    return r;
}
__device__ __forceinline__ float lo32(unsigned long long v) {
    return __uint_as_float((unsigned)(v & 0xffffffffu));
}
__device__ __forceinline__ float hi32(unsigned long long v) {
    return __uint_as_float((unsigned)(v >> 32));
}

// ---------------------------------------------------------------------------
// Index dtype detection + conversion (reference declares int64; JAX default
// x64-off actually yields int32 — detect on device, clamp for safety).
// ---------------------------------------------------------------------------
__global__ void detect_idx_kernel(const int* __restrict__ w32) {
    if (threadIdx.x == 0) {
        int all_zero = 1;
        for (int k = 0; k < 64; k++) {
            if (w32[2 * k * 1024 + 1] != 0) { all_zero = 0; break; }
        }
        g_is64 = all_zero;
    }
}

__global__ void conv_idx_kernel(const int* __restrict__ w32) {
    int i = blockIdx.x * blockDim.x + threadIdx.x;
    if (i >= N_NODES * SEQ) return;
    int v = g_is64 ? w32[2 * i] : w32[i];
    if (v < 0) v = 0;
    if (v >= N_NODES) v = N_NODES - 1;
    g_idx[i] = v;
}

// ---------------------------------------------------------------------------
// fc0: [N,3] @ [3,16]^T + b, ELU. One thread per node.
// ---------------------------------------------------------------------------
__global__ __launch_bounds__(256) void fc0_kernel(
    const float* __restrict__ x,
    const float* __restrict__ w,
    const float* __restrict__ bias)
{
    __shared__ float sw[48];
    __shared__ float sb[16];
    if (threadIdx.x < 48) sw[threadIdx.x] = w[threadIdx.x];
    if (threadIdx.x < 16) sb[threadIdx.x] = bias[threadIdx.x];
    __syncthreads();

    int n = blockIdx.x * blockDim.x + threadIdx.x;
    if (n >= N_NODES) return;

    float x0 = x[n * 3 + 0], x1 = x[n * 3 + 1], x2 = x[n * 3 + 2];
    float o[16];
#pragma unroll
    for (int j = 0; j < 16; j++) {
        float v = sb[j] + sw[j * 3 + 0] * x0 + sw[j * 3 + 1] * x1 + sw[j * 3 + 2] * x2;
        o[j] = elu(v);
    }
    float4* dst = reinterpret_cast<float4*>(g_h0 + (size_t)n * 16);
#pragma unroll
    for (int q = 0; q < 4; q++)
        dst[q] = make_float4(o[4 * q], o[4 * q + 1], o[4 * q + 2], o[4 * q + 3]);
}

// ---------------------------------------------------------------------------
// Gathered GEMM + bias + ELU with packed f32x2 FMAs.
//   out[n, o] = elu( sum_k A[n,k] * w[o,k] + b[o] )
//   A[n,k] = GATHER ? prev[idx[n, k/C] * C + k%C] : prev[n*K + k]
//
// Block tile: BN nodes x OT outputs, BK=32 k-slab.
// Microtile per thread: TM=8 nodes x TO outputs (TO/2 packed accumulators
// per node). THREADS = (BN/8)*(OT/TO).
// smem layout: sA[BK][BN+4], sB[BK][OT+4] (k-major; +4 pad keeps 16B
// alignment of rows and perturbs banks).
// A reads: 2x LDS.128 per k; B reads: TO/2 x LDS.64 per k => 1 B/FMA smem
// traffic, balanced with the 128 FMA/cyc/SM f32x2 pipe.
// ---------------------------------------------------------------------------
template <int C, int K, int O_TOTAL, int BN, int OT, int TO, bool GATHER>
__global__ __launch_bounds__((BN / 8) * (OT / TO)) void gemm_elu_kernel(
    const float* __restrict__ prev,
    float* __restrict__ next,
    const float* __restrict__ w,
    const float* __restrict__ bias)
{
    constexpr int BK = 32, TM = 8;
    constexpr int THREADS = (BN / TM) * (OT / TO);
    constexpr int TX = OT / TO;     // threads along output dim
    constexpr int TOH = TO / 2;     // packed accumulators per node

    __shared__ float sA[BK][BN + 4];
    __shared__ float sB[BK][OT + 4];
    __shared__ int   sIdx[GATHER ? BN * SEQ : 1];

    const int n0    = blockIdx.x * BN;
    const int o_off = blockIdx.y * OT;
    const int t  = threadIdx.x;
    const int tx = t % TX;
    const int ty = t / TX;
    const int n_base = ty * TM;        // node offset within tile
    const int o_base = tx * TO;        // output offset within tile

    if constexpr (GATHER) {
#pragma unroll
        for (int i = t; i < BN * SEQ; i += THREADS) {
            int node = n0 + (i >> 4);            // SEQ == 16
            if (node > N_NODES - 1) node = N_NODES - 1;
            sIdx[i] = g_idx[node * SEQ + (i & 15)];
        }
        __syncthreads();
    }

    unsigned long long acc[TM][TOH];
#pragma unroll
    for (int i = 0; i < TM; i++)
#pragma unroll
        for (int j = 0; j < TOH; j++) acc[i][j] = 0ull;

    for (int k0 = 0; k0 < K; k0 += BK) {
        // ---- A tile (gathered): 32 consecutive threads cover one node's 32
        //      contiguous k => coalesced 128B global reads.
#pragma unroll
        for (int r = 0; r < (BN * BK) / THREADS; r++) {
            int linear = r * THREADS + t;
            int nrow = linear >> 5;
            int kk   = linear & 31;
            int k    = k0 + kk;
            float v;
            if constexpr (GATHER) {
                int src = sIdx[nrow * SEQ + (k / C)];
                v = prev[(size_t)src * C + (k % C)];
            } else {
                int node = n0 + nrow;
                if (node > N_NODES - 1) node = N_NODES - 1;
                v = prev[(size_t)node * K + k];
            }
            sA[kk][nrow] = v;
        }
        // ---- B tile: w is [O_TOTAL, K] row-major, contiguous along k.
#pragma unroll
        for (int r = 0; r < (OT * BK) / THREADS; r++) {
            int linear = r * THREADS + t;
            int o  = linear >> 5;
            int kk = linear & 31;
            sB[kk][o] = w[(size_t)(o_off + o) * K + k0 + kk];
        }
        __syncthreads();

#pragma unroll
        for (int kk = 0; kk < BK; kk++) {
            // A: 8 nodes as 2x float4, duplicated into packed pairs.
            const float4* arow =
                reinterpret_cast<const float4*>(&sA[kk][n_base]);
            float4 a0 = arow[0];
            float4 a1 = arow[1];
            unsigned long long ad[TM];
            ad[0] = dup2(a0.x); ad[1] = dup2(a0.y);
            ad[2] = dup2(a0.z); ad[3] = dup2(a0.w);
            ad[4] = dup2(a1.x); ad[5] = dup2(a1.y);
            ad[6] = dup2(a1.z); ad[7] = dup2(a1.w);
            // B: TO outputs as TO/2 packed 64-bit loads.
            const unsigned long long* brow =
                reinterpret_cast<const unsigned long long*>(&sB[kk][o_base]);
            unsigned long long bv[TOH];
#pragma unroll
            for (int j = 0; j < TOH; j++) bv[j] = brow[j];
#pragma unroll
            for (int i = 0; i < TM; i++)
#pragma unroll
                for (int j = 0; j < TOH; j++)
                    ffma2(acc[i][j], ad[i], bv[j]);
        }
        __syncthreads();
    }

    // ---- Epilogue: bias + ELU, vectorized float4 stores.
    float bb[TO];
#pragma unroll
    for (int j = 0; j < TO; j++) bb[j] = bias[o_off + o_base + j];

#pragma unroll
    for (int i = 0; i < TM; i++) {
        int node = n0 + n_base + i;
        if (node >= N_NODES) break;
        float ov[TO];
#pragma unroll
        for (int j = 0; j < TOH; j++) {
            ov[2 * j]     = elu(lo32(acc[i][j]) + bb[2 * j]);
            ov[2 * j + 1] = elu(hi32(acc[i][j]) + bb[2 * j + 1]);
        }
        float4* dst = reinterpret_cast<float4*>(
            next + (size_t)node * O_TOTAL + o_off + o_base);
#pragma unroll
        for (int q = 0; q < TO / 4; q++)
            dst[q] = make_float4(ov[4 * q], ov[4 * q + 1],
                                 ov[4 * q + 2], ov[4 * q + 3]);
    }
}

// ---------------------------------------------------------------------------
// fc2 + log_softmax: one warp per node. 12 outputs from 256 inputs.
// ---------------------------------------------------------------------------
__global__ __launch_bounds__(256) void fc2_lsm_kernel(
    const float* __restrict__ w,
    const float* __restrict__ bias,
    float* __restrict__ out)
{
    __shared__ float sw[12][256];
    __shared__ float sb[12];
    int t = threadIdx.x;
    for (int i = t; i < 12 * 256; i += 256) sw[i >> 8][i & 255] = w[i];
    if (t < 12) sb[t] = bias[t];
    __syncthreads();

    int node = blockIdx.x * 8 + (t >> 5);
    int lane = t & 31;
    if (node >= N_NODES) return;

    const float* row = g_h4 + (size_t)node * 256;
    float acc[12];
#pragma unroll
    for (int o = 0; o < 12; o++) acc[o] = 0.f;

#pragma unroll
    for (int r = 0; r < 8; r++) {
        float hv = row[lane + 32 * r];
#pragma unroll
        for (int o = 0; o < 12; o++) acc[o] += hv * sw[o][lane + 32 * r];
    }

#pragma unroll
    for (int o = 0; o < 12; o++) {
#pragma unroll
        for (int d = 16; d > 0; d >>= 1)
            acc[o] += __shfl_xor_sync(0xffffffffu, acc[o], d);
        acc[o] += sb[o];
    }

    float m = acc[0];
#pragma unroll
    for (int o = 1; o < 12; o++) m = fmaxf(m, acc[o]);
    float s = 0.f;
#pragma unroll
    for (int o = 0; o < 12; o++) s += expf(acc[o] - m);
    float lse = m + logf(s);

    if (lane < 12) out[(size_t)node * 12 + lane] = acc[lane] - lse;
}

// ---------------------------------------------------------------------------
// Launch
// ---------------------------------------------------------------------------
extern "C" void kernel_launch(void* const* d_in, const int* in_sizes, int n_in,
                              void* d_out, int out_size)
{
    const float* x      = (const float*)d_in[0];
    const int*   idxw   = (const int*)d_in[1];   // raw words; dtype detected on device
    const float* fc0_w  = (const float*)d_in[2];
    const float* fc0_b  = (const float*)d_in[3];
    const float* w1     = (const float*)d_in[4];
    const float* b1     = (const float*)d_in[5];
    const float* w2     = (const float*)d_in[6];
    const float* b2     = (const float*)d_in[7];
    const float* w3     = (const float*)d_in[8];
    const float* b3     = (const float*)d_in[9];
    const float* fc1_w  = (const float*)d_in[10];
    const float* fc1_b  = (const float*)d_in[11];
    const float* fc2_w  = (const float*)d_in[12];
    const float* fc2_b  = (const float*)d_in[13];
    float* out = (float*)d_out;

    float *h0, *h1, *h2, *h3, *h4;
    cudaGetSymbolAddress((void**)&h0, g_h0);
    cudaGetSymbolAddress((void**)&h1, g_h1);
    cudaGetSymbolAddress((void**)&h2, g_h2);
    cudaGetSymbolAddress((void**)&h3, g_h3);
    cudaGetSymbolAddress((void**)&h4, g_h4);

    const int NB = (N_NODES + 127) / 128;   // BN = 128 everywhere

    detect_idx_kernel<<<1, 32>>>(idxw);
    conv_idx_kernel<<<(N_NODES * SEQ + 255) / 256, 256>>>(idxw);
    fc0_kernel<<<(N_NODES + 255) / 256, 256>>>(x, fc0_w, fc0_b);

    // spiral conv 1: C=16,  K=256,  O=32   (BN=128, OT=32,  TO=4 -> 128 thr)
    gemm_elu_kernel<16, 256, 32, 128, 32, 4, true>
        <<<dim3(NB, 1), 128>>>(h0, h1, w1, b1);
    // spiral conv 2: C=32,  K=512,  O=64   (BN=128, OT=64,  TO=8 -> 128 thr)
    gemm_elu_kernel<32, 512, 64, 128, 64, 8, true>
        <<<dim3(NB, 1), 128>>>(h1, h2, w2, b2);
    // spiral conv 3: C=64,  K=1024, O=128  (BN=128, OT=128, TO=8 -> 256 thr)
    gemm_elu_kernel<64, 1024, 128, 128, 128, 8, true>
        <<<dim3(NB, 1), 256>>>(h2, h3, w3, b3);
    // fc1 (dense):   K=128, O=256          (2 output tiles of 128)
    gemm_elu_kernel<128, 128, 256, 128, 128, 8, false>
        <<<dim3(NB, 2), 256>>>(h3, h4, fc1_w, fc1_b);
    // fc2 + log_softmax
    fc2_lsm_kernel<<<(N_NODES + 7) / 8, 256>>>(fc2_w, fc2_b, out);
}

// round 4
// speedup vs baseline: 1.2990x; 1.2990x over previous
#include <cuda_runtime.h>
#include <math.h>

#define N_NODES 100000
#define SEQ 16

// Scratch activations (device globals: no allocation allowed).
__device__ float g_h0[N_NODES * 16];
__device__ float g_h1[N_NODES * 32];
__device__ float g_h2[N_NODES * 64];
__device__ float g_h3[N_NODES * 128];
__device__ float g_h4[N_NODES * 256];
__device__ int   g_idx[N_NODES * SEQ];
__device__ int   g_is64;

__device__ __forceinline__ float elu(float v) {
    return v > 0.f ? v : expm1f(v);
}

// Packed f32x2 helpers (Blackwell FFMA2 — only reachable via PTX).
__device__ __forceinline__ void ffma2(unsigned long long& d,
                                      unsigned long long a,
                                      unsigned long long b) {
    asm("fma.rn.f32x2 %0, %1, %2, %0;" : "+l"(d) : "l"(a), "l"(b));
}
__device__ __forceinline__ unsigned long long dup2(float x) {
    unsigned long long r;
    asm("mov.b64 %0, {%1, %1};" : "=l"(r) : "f"(x));
    return r;
}
__device__ __forceinline__ float lo32(unsigned long long v) {
    return __uint_as_float((unsigned)(v & 0xffffffffu));
}
__device__ __forceinline__ float hi32(unsigned long long v) {
    return __uint_as_float((unsigned)(v >> 32));
}

// ---------------------------------------------------------------------------
// Index dtype detection + conversion (reference declares int64; JAX default
// x64-off actually yields int32 — detect on device, clamp for safety).
// ---------------------------------------------------------------------------
__global__ void detect_idx_kernel(const int* __restrict__ w32) {
    if (threadIdx.x == 0) {
        int all_zero = 1;
        for (int k = 0; k < 64; k++) {
            if (w32[2 * k * 1024 + 1] != 0) { all_zero = 0; break; }
        }
        g_is64 = all_zero;
    }
}

__global__ void conv_idx_kernel(const int* __restrict__ w32) {
    int i = blockIdx.x * blockDim.x + threadIdx.x;
    if (i >= N_NODES * SEQ) return;
    int v = g_is64 ? w32[2 * i] : w32[i];
    if (v < 0) v = 0;
    if (v >= N_NODES) v = N_NODES - 1;
    g_idx[i] = v;
}

// ---------------------------------------------------------------------------
// fc0: [N,3] @ [3,16]^T + b, ELU. One thread per node.
// ---------------------------------------------------------------------------
__global__ __launch_bounds__(256) void fc0_kernel(
    const float* __restrict__ x,
    const float* __restrict__ w,
    const float* __restrict__ bias)
{
    __shared__ float sw[48];
    __shared__ float sb[16];
    if (threadIdx.x < 48) sw[threadIdx.x] = w[threadIdx.x];
    if (threadIdx.x < 16) sb[threadIdx.x] = bias[threadIdx.x];
    __syncthreads();

    int n = blockIdx.x * blockDim.x + threadIdx.x;
    if (n >= N_NODES) return;

    float x0 = x[n * 3 + 0], x1 = x[n * 3 + 1], x2 = x[n * 3 + 2];
    float o[16];
#pragma unroll
    for (int j = 0; j < 16; j++) {
        float v = sb[j] + sw[j * 3 + 0] * x0 + sw[j * 3 + 1] * x1 + sw[j * 3 + 2] * x2;
        o[j] = elu(v);
    }
    float4* dst = reinterpret_cast<float4*>(g_h0 + (size_t)n * 16);
#pragma unroll
    for (int q = 0; q < 4; q++)
        dst[q] = make_float4(o[4 * q], o[4 * q + 1], o[4 * q + 2], o[4 * q + 3]);
}

// ---------------------------------------------------------------------------
// Gathered GEMM + bias + ELU, packed f32x2 FMAs, double-buffered smem with
// register prefetch (LDG for tile s+1 issued before computing tile s).
//
//   out[n, o] = elu( sum_k A[n,k] * w[o,k] + b[o] )
//   A[n,k] = GATHER ? prev[idx[n, k/C] * C + k%C] : prev[n*K + k]
//
// BN nodes x OT outputs per block, BK=16 k-slab, THREADS=(BN/TM)*(OT/TO).
// Microtile TM nodes x TO outputs per thread (TO/2 packed f32x2 accums).
// smem k-major: sA[2][BK][BN+4], sB[2][BK][OT+4] -> LDS.128 reads.
// ---------------------------------------------------------------------------
template <int C, int K, int O_TOTAL, int BN, int OT, int TM, int TO, bool GATHER>
__global__ __launch_bounds__((BN / TM) * (OT / TO)) void gemm_elu_kernel(
    const float* __restrict__ prev,
    float* __restrict__ next,
    const float* __restrict__ w,
    const float* __restrict__ bias)
{
    constexpr int BK      = 16;
    constexpr int THREADS = (BN / TM) * (OT / TO);
    constexpr int TX      = OT / TO;
    constexpr int TOH     = TO / 2;
    constexpr int AR      = (BN * BK) / THREADS;   // A elems per thread
    constexpr int BR      = (OT * BK) / THREADS;   // B elems per thread
    constexpr int NSTEP   = K / BK;
    constexpr int LOG2C   = (C == 16) ? 4 : (C == 32) ? 5 : (C == 64) ? 6 : 7;
    constexpr int ROWS16  = THREADS / 16;          // rows covered per load pass

    __shared__ float sA[2][BK][BN + 4];
    __shared__ float sB[2][BK][OT + 4];
    __shared__ int   sIdx[GATHER ? BN * SEQ : 1];

    const int n0    = blockIdx.x * BN;
    const int o_off = blockIdx.y * OT;
    const int t  = threadIdx.x;
    const int tx = t % TX;
    const int ty = t / TX;
    const int n_base = ty * TM;
    const int o_base = tx * TO;

    // fixed loader coordinates: 16 consecutive threads cover one row's 16 k's
    const int lkk  = t & 15;         // k within slab (A and B)
    const int lrow = t >> 4;         // row offset base

    if constexpr (GATHER) {
#pragma unroll
        for (int i = t; i < BN * SEQ; i += THREADS) {
            int node = n0 + (i >> 4);            // SEQ == 16
            if (node > N_NODES - 1) node = N_NODES - 1;
            sIdx[i] = g_idx[node * SEQ + (i & 15)];
        }
        __syncthreads();
    }

    float pa[AR], pb[BR];

    // ---- tile loader into registers (global -> regs) ----
    auto load_tile = [&](int step) {
        const int k0 = step * BK;
        const int k  = k0 + lkk;
#pragma unroll
        for (int r = 0; r < AR; r++) {
            int nrow = r * ROWS16 + lrow;
            if constexpr (GATHER) {
                int src = sIdx[nrow * SEQ + (k >> LOG2C)];
                pa[r] = prev[(size_t)src * C + (k & (C - 1))];
            } else {
                int node = n0 + nrow;
                if (node > N_NODES - 1) node = N_NODES - 1;
                pa[r] = prev[(size_t)node * K + k];
            }
        }
#pragma unroll
        for (int r = 0; r < BR; r++) {
            int o = r * ROWS16 + lrow;
            pb[r] = w[(size_t)(o_off + o) * K + k];
        }
    };
    // ---- regs -> smem buffer ----
    auto store_tile = [&](int buf) {
#pragma unroll
        for (int r = 0; r < AR; r++)
            sA[buf][lkk][r * ROWS16 + lrow] = pa[r];
#pragma unroll
        for (int r = 0; r < BR; r++)
            sB[buf][lkk][r * ROWS16 + lrow] = pb[r];
    };

    unsigned long long acc[TM][TOH];
#pragma unroll
    for (int i = 0; i < TM; i++)
#pragma unroll
        for (int j = 0; j < TOH; j++) acc[i][j] = 0ull;

    load_tile(0);
    store_tile(0);
    __syncthreads();

    int p = 0;
    for (int step = 0; step < NSTEP; ++step) {
        if (step + 1 < NSTEP) load_tile(step + 1);   // LDGs in flight

#pragma unroll
        for (int kk = 0; kk < BK; kk++) {
            const float4* arow =
                reinterpret_cast<const float4*>(&sA[p][kk][n_base]);
            unsigned long long ad[TM];
#pragma unroll
            for (int q = 0; q < TM / 4; q++) {
                float4 av = arow[q];
                ad[4 * q + 0] = dup2(av.x);
                ad[4 * q + 1] = dup2(av.y);
                ad[4 * q + 2] = dup2(av.z);
                ad[4 * q + 3] = dup2(av.w);
            }
            const unsigned long long* brow =
                reinterpret_cast<const unsigned long long*>(&sB[p][kk][o_base]);
            unsigned long long bv[TOH];
#pragma unroll
            for (int j = 0; j < TOH; j++) bv[j] = brow[j];
#pragma unroll
            for (int i = 0; i < TM; i++)
#pragma unroll
                for (int j = 0; j < TOH; j++)
                    ffma2(acc[i][j], ad[i], bv[j]);
        }

        if (step + 1 < NSTEP) store_tile(p ^ 1);
        __syncthreads();
        p ^= 1;
    }

    // ---- Epilogue: bias + ELU, vectorized float4 stores.
    float bb[TO];
#pragma unroll
    for (int j = 0; j < TO; j++) bb[j] = bias[o_off + o_base + j];

#pragma unroll
    for (int i = 0; i < TM; i++) {
        int node = n0 + n_base + i;
        if (node >= N_NODES) break;
        float ov[TO];
#pragma unroll
        for (int j = 0; j < TOH; j++) {
            ov[2 * j]     = elu(lo32(acc[i][j]) + bb[2 * j]);
            ov[2 * j + 1] = elu(hi32(acc[i][j]) + bb[2 * j + 1]);
        }
        float4* dst = reinterpret_cast<float4*>(
            next + (size_t)node * O_TOTAL + o_off + o_base);
#pragma unroll
        for (int q = 0; q < TO / 4; q++)
            dst[q] = make_float4(ov[4 * q], ov[4 * q + 1],
                                 ov[4 * q + 2], ov[4 * q + 3]);
    }
}

// ---------------------------------------------------------------------------
// fc2 + log_softmax: one warp per node. 12 outputs from 256 inputs.
// ---------------------------------------------------------------------------
__global__ __launch_bounds__(256) void fc2_lsm_kernel(
    const float* __restrict__ w,
    const float* __restrict__ bias,
    float* __restrict__ out)
{
    __shared__ float sw[12][256];
    __shared__ float sb[12];
    int t = threadIdx.x;
    for (int i = t; i < 12 * 256; i += 256) sw[i >> 8][i & 255] = w[i];
    if (t < 12) sb[t] = bias[t];
    __syncthreads();

    int node = blockIdx.x * 8 + (t >> 5);
    int lane = t & 31;
    if (node >= N_NODES) return;

    const float* row = g_h4 + (size_t)node * 256;
    float acc[12];
#pragma unroll
    for (int o = 0; o < 12; o++) acc[o] = 0.f;

#pragma unroll
    for (int r = 0; r < 8; r++) {
        float hv = row[lane + 32 * r];
#pragma unroll
        for (int o = 0; o < 12; o++) acc[o] += hv * sw[o][lane + 32 * r];
    }

#pragma unroll
    for (int o = 0; o < 12; o++) {
#pragma unroll
        for (int d = 16; d > 0; d >>= 1)
            acc[o] += __shfl_xor_sync(0xffffffffu, acc[o], d);
        acc[o] += sb[o];
    }

    float m = acc[0];
#pragma unroll
    for (int o = 1; o < 12; o++) m = fmaxf(m, acc[o]);
    float s = 0.f;
#pragma unroll
    for (int o = 0; o < 12; o++) s += expf(acc[o] - m);
    float lse = m + logf(s);

    if (lane < 12) out[(size_t)node * 12 + lane] = acc[lane] - lse;
}

// ---------------------------------------------------------------------------
// Launch
// ---------------------------------------------------------------------------
extern "C" void kernel_launch(void* const* d_in, const int* in_sizes, int n_in,
                              void* d_out, int out_size)
{
    const float* x      = (const float*)d_in[0];
    const int*   idxw   = (const int*)d_in[1];   // raw words; dtype detected on device
    const float* fc0_w  = (const float*)d_in[2];
    const float* fc0_b  = (const float*)d_in[3];
    const float* w1     = (const float*)d_in[4];
    const float* b1     = (const float*)d_in[5];
    const float* w2     = (const float*)d_in[6];
    const float* b2     = (const float*)d_in[7];
    const float* w3     = (const float*)d_in[8];
    const float* b3     = (const float*)d_in[9];
    const float* fc1_w  = (const float*)d_in[10];
    const float* fc1_b  = (const float*)d_in[11];
    const float* fc2_w  = (const float*)d_in[12];
    const float* fc2_b  = (const float*)d_in[13];
    float* out = (float*)d_out;

    float *h0, *h1, *h2, *h3, *h4;
    cudaGetSymbolAddress((void**)&h0, g_h0);
    cudaGetSymbolAddress((void**)&h1, g_h1);
    cudaGetSymbolAddress((void**)&h2, g_h2);
    cudaGetSymbolAddress((void**)&h3, g_h3);
    cudaGetSymbolAddress((void**)&h4, g_h4);

    const int NB = (N_NODES + 127) / 128;   // BN = 128 everywhere

    detect_idx_kernel<<<1, 32>>>(idxw);
    conv_idx_kernel<<<(N_NODES * SEQ + 255) / 256, 256>>>(idxw);
    fc0_kernel<<<(N_NODES + 255) / 256, 256>>>(x, fc0_w, fc0_b);

    // spiral conv 1: C=16,  K=256,  O=32   (TM=4, TO=4 -> 256 thr)
    gemm_elu_kernel<16, 256, 32, 128, 32, 4, 4, true>
        <<<dim3(NB, 1), 256>>>(h0, h1, w1, b1);
    // spiral conv 2: C=32,  K=512,  O=64   (TM=4, TO=8 -> 256 thr)
    gemm_elu_kernel<32, 512, 64, 128, 64, 4, 8, true>
        <<<dim3(NB, 1), 256>>>(h1, h2, w2, b2);
    // spiral conv 3: C=64,  K=1024, O=128  (TM=8, TO=8 -> 256 thr)
    gemm_elu_kernel<64, 1024, 128, 128, 128, 8, 8, true>
        <<<dim3(NB, 1), 256>>>(h2, h3, w3, b3);
    // fc1 (dense):   K=128, O=256          (2 output tiles of 128)
    gemm_elu_kernel<128, 128, 256, 128, 128, 8, 8, false>
        <<<dim3(NB, 2), 256>>>(h3, h4, fc1_w, fc1_b);
    // fc2 + log_softmax
    fc2_lsm_kernel<<<(N_NODES + 7) / 8, 256>>>(fc2_w, fc2_b, out);
}

// round 6
// speedup vs baseline: 2.1617x; 1.6642x over previous
#include <cuda_runtime.h>
#include <cuda_bf16.h>
#include <math.h>
#include <stdint.h>

#define N_NODES 100000
#define SEQ 16

// Scratch activations (device globals: no allocation allowed).
__device__ __align__(16) float g_h0[N_NODES * 16];
__device__ __align__(16) float g_h1[N_NODES * 32];
__device__ __align__(16) float g_h2[N_NODES * 64];
__device__ __align__(16) float g_h3[N_NODES * 128];
__device__ __align__(16) float g_h4[N_NODES * 256];
__device__ int   g_idx[N_NODES * SEQ];
__device__ int   g_is64;
// weights split into bf16 hi/lo (prepared once per launch)
__device__ __align__(16) __nv_bfloat16 g_w2h[64 * 512];
__device__ __align__(16) __nv_bfloat16 g_w2l[64 * 512];
__device__ __align__(16) __nv_bfloat16 g_w3h[128 * 1024];
__device__ __align__(16) __nv_bfloat16 g_w3l[128 * 1024];
__device__ __align__(16) __nv_bfloat16 g_f1h[256 * 128];
__device__ __align__(16) __nv_bfloat16 g_f1l[256 * 128];

__device__ __forceinline__ float elu(float v) {
    return v > 0.f ? v : expm1f(v);
}

// ---------------- packed f32x2 helpers (FFMA2 path, layer 1) ----------------
__device__ __forceinline__ void ffma2(unsigned long long& d,
                                      unsigned long long a,
                                      unsigned long long b) {
    asm("fma.rn.f32x2 %0, %1, %2, %0;" : "+l"(d) : "l"(a), "l"(b));
}
__device__ __forceinline__ unsigned long long dup2(float x) {
    unsigned long long r;
    asm("mov.b64 %0, {%1, %1};" : "=l"(r) : "f"(x));
    return r;
}
__device__ __forceinline__ float lo32(unsigned long long v) {
    return __uint_as_float((unsigned)(v & 0xffffffffu));
}
__device__ __forceinline__ float hi32(unsigned long long v) {
    return __uint_as_float((unsigned)(v >> 32));
}

// ---------------- warp-mma helpers (sm_80+ baseline ops) ----------------
__device__ __forceinline__ uint32_t smem_to_u32(const void* p) {
    uint32_t a;
    asm("{ .reg .u64 tmp; cvta.to.shared.u64 tmp, %1; cvt.u32.u64 %0, tmp; }"
        : "=r"(a) : "l"(p));
    return a;
}
#define SWZ(b) ((b) ^ (((b) >> 3) & 0x70))

__device__ __forceinline__ void ldsm_x4(uint32_t* r, uint32_t addr) {
    asm volatile(
        "ldmatrix.sync.aligned.m8n8.x4.shared.b16 {%0,%1,%2,%3}, [%4];"
        : "=r"(r[0]), "=r"(r[1]), "=r"(r[2]), "=r"(r[3]) : "r"(addr));
}
__device__ __forceinline__ void mma_bf16(float* c, const uint32_t* a,
                                         uint32_t b0, uint32_t b1) {
    asm volatile(
        "mma.sync.aligned.m16n8k16.row.col.f32.bf16.bf16.f32 "
        "{%0,%1,%2,%3}, {%4,%5,%6,%7}, {%8,%9}, {%0,%1,%2,%3};"
        : "+f"(c[0]), "+f"(c[1]), "+f"(c[2]), "+f"(c[3])
        : "r"(a[0]), "r"(a[1]), "r"(a[2]), "r"(a[3]), "r"(b0), "r"(b1));
}

__device__ __forceinline__ uint32_t pack_hi2(float a, float b,
                                             float& la, float& lb) {
    __nv_bfloat162 h = __floats2bfloat162_rn(a, b);
    la = a - __bfloat162float(__low2bfloat16(h));
    lb = b - __bfloat162float(__high2bfloat16(h));
    return *reinterpret_cast<uint32_t*>(&h);
}
__device__ __forceinline__ uint32_t pack_lo2(float a, float b) {
    __nv_bfloat162 l = __floats2bfloat162_rn(a, b);
    return *reinterpret_cast<uint32_t*>(&l);
}

// ---------------------------------------------------------------------------
// Index dtype detection + conversion (reference declares int64; JAX default
// x64-off actually yields int32 — detect on device, clamp for safety).
// ---------------------------------------------------------------------------
__global__ void detect_idx_kernel(const int* __restrict__ w32) {
    if (threadIdx.x == 0) {
        int all_zero = 1;
        for (int k = 0; k < 64; k++) {
            if (w32[2 * k * 1024 + 1] != 0) { all_zero = 0; break; }
        }
        g_is64 = all_zero;
    }
}
__global__ void conv_idx_kernel(const int* __restrict__ w32) {
    int i = blockIdx.x * blockDim.x + threadIdx.x;
    if (i >= N_NODES * SEQ) return;
    int v = g_is64 ? w32[2 * i] : w32[i];
    if (v < 0) v = 0;
    if (v >= N_NODES) v = N_NODES - 1;
    g_idx[i] = v;
}

// ---------------------------------------------------------------------------
// fp32 -> bf16 hi/lo weight split
// ---------------------------------------------------------------------------
__global__ void split_kernel(const float* __restrict__ w,
                             __nv_bfloat16* __restrict__ hi,
                             __nv_bfloat16* __restrict__ lo, int n) {
    int i = blockIdx.x * blockDim.x + threadIdx.x;
    if (i >= n) return;
    float v = w[i];
    __nv_bfloat16 h = __float2bfloat16(v);
    hi[i] = h;
    lo[i] = __float2bfloat16(v - __bfloat162float(h));
}

// ---------------------------------------------------------------------------
// fc0: [N,3] @ [3,16]^T + b, ELU. One thread per node.
// ---------------------------------------------------------------------------
__global__ __launch_bounds__(256) void fc0_kernel(
    const float* __restrict__ x,
    const float* __restrict__ w,
    const float* __restrict__ bias)
{
    __shared__ float sw[48];
    __shared__ float sb[16];
    if (threadIdx.x < 48) sw[threadIdx.x] = w[threadIdx.x];
    if (threadIdx.x < 16) sb[threadIdx.x] = bias[threadIdx.x];
    __syncthreads();

    int n = blockIdx.x * blockDim.x + threadIdx.x;
    if (n >= N_NODES) return;

    float x0 = x[n * 3 + 0], x1 = x[n * 3 + 1], x2 = x[n * 3 + 2];
    float o[16];
#pragma unroll
    for (int j = 0; j < 16; j++) {
        float v = sb[j] + sw[j * 3 + 0] * x0 + sw[j * 3 + 1] * x1 + sw[j * 3 + 2] * x2;
        o[j] = elu(v);
    }
    float4* dst = reinterpret_cast<float4*>(g_h0 + (size_t)n * 16);
#pragma unroll
    for (int q = 0; q < 4; q++)
        dst[q] = make_float4(o[4 * q], o[4 * q + 1], o[4 * q + 2], o[4 * q + 3]);
}

// ---------------------------------------------------------------------------
// FFMA2 gathered GEMM (layer 1 only) — unchanged from R4.
// ---------------------------------------------------------------------------
template <int C, int K, int O_TOTAL, int BN, int OT, int TM, int TO, bool GATHER>
__global__ __launch_bounds__((BN / TM) * (OT / TO)) void gemm_elu_kernel(
    const float* __restrict__ prev,
    float* __restrict__ next,
    const float* __restrict__ w,
    const float* __restrict__ bias)
{
    constexpr int BK      = 16;
    constexpr int THREADS = (BN / TM) * (OT / TO);
    constexpr int TX      = OT / TO;
    constexpr int TOH     = TO / 2;
    constexpr int AR      = (BN * BK) / THREADS;
    constexpr int BR      = (OT * BK) / THREADS;
    constexpr int NSTEP   = K / BK;
    constexpr int LOG2C   = (C == 16) ? 4 : (C == 32) ? 5 : (C == 64) ? 6 : 7;
    constexpr int ROWS16  = THREADS / 16;

    __shared__ float sA[2][BK][BN + 4];
    __shared__ float sB[2][BK][OT + 4];
    __shared__ int   sIdx[GATHER ? BN * SEQ : 1];

    const int n0    = blockIdx.x * BN;
    const int o_off = blockIdx.y * OT;
    const int t  = threadIdx.x;
    const int tx = t % TX;
    const int ty = t / TX;
    const int n_base = ty * TM;
    const int o_base = tx * TO;

    const int lkk  = t & 15;
    const int lrow = t >> 4;

    if constexpr (GATHER) {
#pragma unroll
        for (int i = t; i < BN * SEQ; i += THREADS) {
            int node = n0 + (i >> 4);
            if (node > N_NODES - 1) node = N_NODES - 1;
            sIdx[i] = g_idx[node * SEQ + (i & 15)];
        }
        __syncthreads();
    }

    float pa[AR], pb[BR];

    auto load_tile = [&](int step) {
        const int k = step * BK + lkk;
#pragma unroll
        for (int r = 0; r < AR; r++) {
            int nrow = r * ROWS16 + lrow;
            if constexpr (GATHER) {
                int src = sIdx[nrow * SEQ + (k >> LOG2C)];
                pa[r] = prev[(size_t)src * C + (k & (C - 1))];
            } else {
                int node = n0 + nrow;
                if (node > N_NODES - 1) node = N_NODES - 1;
                pa[r] = prev[(size_t)node * K + k];
            }
        }
#pragma unroll
        for (int r = 0; r < BR; r++) {
            int o = r * ROWS16 + lrow;
            pb[r] = w[(size_t)(o_off + o) * K + k];
        }
    };
    auto store_tile = [&](int buf) {
#pragma unroll
        for (int r = 0; r < AR; r++)
            sA[buf][lkk][r * ROWS16 + lrow] = pa[r];
#pragma unroll
        for (int r = 0; r < BR; r++)
            sB[buf][lkk][r * ROWS16 + lrow] = pb[r];
    };

    unsigned long long acc[TM][TOH];
#pragma unroll
    for (int i = 0; i < TM; i++)
#pragma unroll
        for (int j = 0; j < TOH; j++) acc[i][j] = 0ull;

    load_tile(0);
    store_tile(0);
    __syncthreads();

    int p = 0;
    for (int step = 0; step < NSTEP; ++step) {
        if (step + 1 < NSTEP) load_tile(step + 1);

#pragma unroll
        for (int kk = 0; kk < BK; kk++) {
            const float4* arow =
                reinterpret_cast<const float4*>(&sA[p][kk][n_base]);
            unsigned long long ad[TM];
#pragma unroll
            for (int q = 0; q < TM / 4; q++) {
                float4 av = arow[q];
                ad[4 * q + 0] = dup2(av.x);
                ad[4 * q + 1] = dup2(av.y);
                ad[4 * q + 2] = dup2(av.z);
                ad[4 * q + 3] = dup2(av.w);
            }
            const unsigned long long* brow =
                reinterpret_cast<const unsigned long long*>(&sB[p][kk][o_base]);
            unsigned long long bv[TOH];
#pragma unroll
            for (int j = 0; j < TOH; j++) bv[j] = brow[j];
#pragma unroll
            for (int i = 0; i < TM; i++)
#pragma unroll
                for (int j = 0; j < TOH; j++)
                    ffma2(acc[i][j], ad[i], bv[j]);
        }

        if (step + 1 < NSTEP) store_tile(p ^ 1);
        __syncthreads();
        p ^= 1;
    }

    float bb[TO];
#pragma unroll
    for (int j = 0; j < TO; j++) bb[j] = bias[o_off + o_base + j];

#pragma unroll
    for (int i = 0; i < TM; i++) {
        int node = n0 + n_base + i;
        if (node >= N_NODES) break;
        float ov[TO];
#pragma unroll
        for (int j = 0; j < TOH; j++) {
            ov[2 * j]     = elu(lo32(acc[i][j]) + bb[2 * j]);
            ov[2 * j + 1] = elu(hi32(acc[i][j]) + bb[2 * j + 1]);
        }
        float4* dst = reinterpret_cast<float4*>(
            next + (size_t)node * O_TOTAL + o_off + o_base);
#pragma unroll
        for (int q = 0; q < TO / 4; q++)
            dst[q] = make_float4(ov[4 * q], ov[4 * q + 1],
                                 ov[4 * q + 2], ov[4 * q + 3]);
    }
}

// ---------------------------------------------------------------------------
// Warp-MMA gathered GEMM (layers 2, 3, fc1): bf16 hi/lo split, fp32 accum.
//   out[n,o] = elu( sum_k A[n,k]*w[o,k] + b[o] ),  3 terms per product:
//   Ahi*Whi + Ahi*Wlo + Alo*Whi  (err ~2^-16, budget 1e-3).
//
// BM=128 nodes x OT outputs per block. BK=64 (bf16) k-slab; for gather,
// a slab covers whole neighbor rows (C=64: 1 nbr; C=32: 2 nbrs). 8 warps
// as (wm 0..3, wn 0..1): warp tile 32 x WN (WN=OT/2).
// smem: swizzled [row][64] bf16 tiles for Ahi/Alo/Bhi/Blo; ldmatrix.x4
// fragments; mma.sync m16n8k16 row.col. Register-prefetch of slab s+1.
// C==0 means dense (no gather).
// ---------------------------------------------------------------------------
template <int K, int O_TOTAL, int OT, int C>
__global__ __launch_bounds__(256, 1) void mma_gemm_kernel(
    const float* __restrict__ prev,
    float* __restrict__ next,
    const __nv_bfloat16* __restrict__ wh,
    const __nv_bfloat16* __restrict__ wl,
    const float* __restrict__ bias)
{
    constexpr int NSLAB = K / 64;
    constexpr int WN    = OT / 2;        // warp n-extent
    constexpr int NT    = WN / 8;        // n8 tiles per warp
    constexpr int NT2   = WN / 16;       // x4 b-load groups
    constexpr int BCH   = OT * 8 / 256;  // B 16B-chunks per thread (per hi/lo)

    // smem byte offsets (each tile 1024-aligned)
    constexpr uint32_t AHI = 0;
    constexpr uint32_t ALO = 128 * 128;           // 16 KB
    constexpr uint32_t BHI = 2 * 128 * 128;       // 32 KB
    constexpr uint32_t BLO = BHI + OT * 128;

    extern __shared__ char smem[];
    const uint32_t sb = smem_to_u32(smem);

    const int t     = threadIdx.x;
    const int wid   = t >> 5;
    const int lane  = t & 31;
    const int wm    = wid & 3;
    const int wn    = wid >> 2;
    const int gid   = lane >> 2;
    const int tid   = lane & 3;
    const int n0    = blockIdx.x * 128;
    const int o_off = blockIdx.y * OT;

    // loader coords: row = t/2 (0..127), half = t&1 (32 floats each)
    const int lrow  = t >> 1;
    const int lhalf = t & 1;
    int lnode = n0 + lrow;
    if (lnode > N_NODES - 1) lnode = N_NODES - 1;

    float4   av[8];     // 32 fp32 of A row-half
    uint4    bh[BCH], bl[BCH];

    auto load_regs = [&](int s) {
        const float* src;
        if constexpr (C == 0) {
            src = prev + (size_t)lnode * K + s * 64 + lhalf * 32;
        } else {
            int kg  = s * 64 + lhalf * 32;
            int nb  = kg / C;
            int col = kg % C;
            int sn  = g_idx[lnode * SEQ + nb];
            src = prev + (size_t)sn * C + col;
        }
        const float4* s4 = reinterpret_cast<const float4*>(src);
#pragma unroll
        for (int c = 0; c < 8; c++) av[c] = s4[c];
#pragma unroll
        for (int j = 0; j < BCH; j++) {
            int id  = t + 256 * j;
            int o   = id >> 3;
            int seg = id & 7;
            const char* gp = reinterpret_cast<const char*>(wh) +
                             (size_t)(o_off + o) * (2 * K) + s * 128 + seg * 16;
            const char* gl = reinterpret_cast<const char*>(wl) +
                             (size_t)(o_off + o) * (2 * K) + s * 128 + seg * 16;
            bh[j] = *reinterpret_cast<const uint4*>(gp);
            bl[j] = *reinterpret_cast<const uint4*>(gl);
        }
    };
    auto sts = [&]() {
#pragma unroll
        for (int c = 0; c < 4; c++) {
            float4 x = av[2 * c];
            float4 y = av[2 * c + 1];
            float l0, l1, l2, l3, l4, l5, l6, l7;
            uint4 hi, lo;
            hi.x = pack_hi2(x.x, x.y, l0, l1);
            hi.y = pack_hi2(x.z, x.w, l2, l3);
            hi.z = pack_hi2(y.x, y.y, l4, l5);
            hi.w = pack_hi2(y.z, y.w, l6, l7);
            lo.x = pack_lo2(l0, l1);
            lo.y = pack_lo2(l2, l3);
            lo.z = pack_lo2(l4, l5);
            lo.w = pack_lo2(l6, l7);
            uint32_t off = (uint32_t)(lrow * 128 + lhalf * 64 + c * 16);
            uint32_t sw  = SWZ(off);
            *reinterpret_cast<uint4*>(smem + AHI + sw) = hi;
            *reinterpret_cast<uint4*>(smem + ALO + sw) = lo;
        }
#pragma unroll
        for (int j = 0; j < BCH; j++) {
            int id  = t + 256 * j;
            int o   = id >> 3;
            int seg = id & 7;
            uint32_t sw = SWZ((uint32_t)(o * 128 + seg * 16));
            *reinterpret_cast<uint4*>(smem + BHI + sw) = bh[j];
            *reinterpret_cast<uint4*>(smem + BLO + sw) = bl[j];
        }
    };

    float acc[2][NT][4];
#pragma unroll
    for (int m = 0; m < 2; m++)
#pragma unroll
        for (int n = 0; n < NT; n++)
#pragma unroll
            for (int q = 0; q < 4; q++) acc[m][n][q] = 0.f;

    load_regs(0);
    sts();
    __syncthreads();

    for (int s = 0; s < NSLAB; s++) {
        if (s + 1 < NSLAB) load_regs(s + 1);

        // ---- compute slab s from smem ----
        const uint32_t flrow  = lane & 15;
        const uint32_t fchalf = (lane >> 4) * 16;
#pragma unroll
        for (int kc = 0; kc < 4; kc++) {
            uint32_t colb = kc * 32 + fchalf;
            uint32_t ah[2][4], al[2][4];
#pragma unroll
            for (int mt = 0; mt < 2; mt++) {
                uint32_t off = (wm * 32 + mt * 16 + flrow) * 128 + colb;
                uint32_t sw  = SWZ(off);
                ldsm_x4(ah[mt], sb + AHI + sw);
                ldsm_x4(al[mt], sb + ALO + sw);
            }
#pragma unroll
            for (int n2 = 0; n2 < NT2; n2++) {
                uint32_t off = (wn * WN + n2 * 16 + flrow) * 128 + colb;
                uint32_t sw  = SWZ(off);
                uint32_t fh[4], fl[4];
                ldsm_x4(fh, sb + BHI + sw);
                ldsm_x4(fl, sb + BLO + sw);
#pragma unroll
                for (int mt = 0; mt < 2; mt++) {
                    mma_bf16(acc[mt][n2 * 2],     ah[mt], fh[0], fh[2]);
                    mma_bf16(acc[mt][n2 * 2],     ah[mt], fl[0], fl[2]);
                    mma_bf16(acc[mt][n2 * 2],     al[mt], fh[0], fh[2]);
                    mma_bf16(acc[mt][n2 * 2 + 1], ah[mt], fh[1], fh[3]);
                    mma_bf16(acc[mt][n2 * 2 + 1], ah[mt], fl[1], fl[3]);
                    mma_bf16(acc[mt][n2 * 2 + 1], al[mt], fh[1], fh[3]);
                }
            }
        }

        __syncthreads();                 // all warps done reading smem
        if (s + 1 < NSLAB) {
            sts();
            __syncthreads();
        }
    }

    // ---- epilogue: bias + ELU, float2 stores ----
#pragma unroll
    for (int mt = 0; mt < 2; mt++) {
#pragma unroll
        for (int nt = 0; nt < NT; nt++) {
            int col = o_off + wn * WN + nt * 8 + tid * 2;
            float b0 = bias[col], b1 = bias[col + 1];
            int r0 = n0 + wm * 32 + mt * 16 + gid;
            if (r0 < N_NODES) {
                float2 v;
                v.x = elu(acc[mt][nt][0] + b0);
                v.y = elu(acc[mt][nt][1] + b1);
                *reinterpret_cast<float2*>(next + (size_t)r0 * O_TOTAL + col) = v;
            }
            int r1 = r0 + 8;
            if (r1 < N_NODES) {
                float2 v;
                v.x = elu(acc[mt][nt][2] + b0);
                v.y = elu(acc[mt][nt][3] + b1);
                *reinterpret_cast<float2*>(next + (size_t)r1 * O_TOTAL + col) = v;
            }
        }
    }
}

// ---------------------------------------------------------------------------
// fc2 + log_softmax: one warp per node. 12 outputs from 256 inputs.
// ---------------------------------------------------------------------------
__global__ __launch_bounds__(256) void fc2_lsm_kernel(
    const float* __restrict__ w,
    const float* __restrict__ bias,
    float* __restrict__ out)
{
    __shared__ float sw[12][256];
    __shared__ float sb[12];
    int t = threadIdx.x;
    for (int i = t; i < 12 * 256; i += 256) sw[i >> 8][i & 255] = w[i];
    if (t < 12) sb[t] = bias[t];
    __syncthreads();

    int node = blockIdx.x * 8 + (t >> 5);
    int lane = t & 31;
    if (node >= N_NODES) return;

    const float* row = g_h4 + (size_t)node * 256;
    float acc[12];
#pragma unroll
    for (int o = 0; o < 12; o++) acc[o] = 0.f;

#pragma unroll
    for (int r = 0; r < 8; r++) {
        float hv = row[lane + 32 * r];
#pragma unroll
        for (int o = 0; o < 12; o++) acc[o] += hv * sw[o][lane + 32 * r];
    }

#pragma unroll
    for (int o = 0; o < 12; o++) {
#pragma unroll
        for (int d = 16; d > 0; d >>= 1)
            acc[o] += __shfl_xor_sync(0xffffffffu, acc[o], d);
        acc[o] += sb[o];
    }

    float m = acc[0];
#pragma unroll
    for (int o = 1; o < 12; o++) m = fmaxf(m, acc[o]);
    float s = 0.f;
#pragma unroll
    for (int o = 0; o < 12; o++) s += expf(acc[o] - m);
    float lse = m + logf(s);

    if (lane < 12) out[(size_t)node * 12 + lane] = acc[lane] - lse;
}

// ---------------------------------------------------------------------------
// Launch
// ---------------------------------------------------------------------------
extern "C" void kernel_launch(void* const* d_in, const int* in_sizes, int n_in,
                              void* d_out, int out_size)
{
    const float* x      = (const float*)d_in[0];
    const int*   idxw   = (const int*)d_in[1];
    const float* fc0_w  = (const float*)d_in[2];
    const float* fc0_b  = (const float*)d_in[3];
    const float* w1     = (const float*)d_in[4];
    const float* b1     = (const float*)d_in[5];
    const float* w2     = (const float*)d_in[6];
    const float* b2     = (const float*)d_in[7];
    const float* w3     = (const float*)d_in[8];
    const float* b3     = (const float*)d_in[9];
    const float* fc1_w  = (const float*)d_in[10];
    const float* fc1_b  = (const float*)d_in[11];
    const float* fc2_w  = (const float*)d_in[12];
    const float* fc2_b  = (const float*)d_in[13];
    float* out = (float*)d_out;

    float *h0, *h1, *h2, *h3, *h4;
    cudaGetSymbolAddress((void**)&h0, g_h0);
    cudaGetSymbolAddress((void**)&h1, g_h1);
    cudaGetSymbolAddress((void**)&h2, g_h2);
    cudaGetSymbolAddress((void**)&h3, g_h3);
    cudaGetSymbolAddress((void**)&h4, g_h4);

    __nv_bfloat16 *w2h, *w2l, *w3h, *w3l, *f1h, *f1l;
    cudaGetSymbolAddress((void**)&w2h, g_w2h);
    cudaGetSymbolAddress((void**)&w2l, g_w2l);
    cudaGetSymbolAddress((void**)&w3h, g_w3h);
    cudaGetSymbolAddress((void**)&w3l, g_w3l);
    cudaGetSymbolAddress((void**)&f1h, g_f1h);
    cudaGetSymbolAddress((void**)&f1l, g_f1l);

    // dynamic smem sizes: A 32KB + B (OT*128*2) bytes
    const int SM_L2  = 32768 + 64 * 128 * 2;    // 48 KB
    const int SM_L3  = 32768 + 128 * 128 * 2;   // 64 KB
    const int SM_FC1 = SM_L3;

    static int attr_set = 0;
    if (!attr_set) {
        cudaFuncSetAttribute(mma_gemm_kernel<512, 64, 64, 32>,
                             cudaFuncAttributeMaxDynamicSharedMemorySize, SM_L2);
        cudaFuncSetAttribute(mma_gemm_kernel<1024, 128, 128, 64>,
                             cudaFuncAttributeMaxDynamicSharedMemorySize, SM_L3);
        cudaFuncSetAttribute(mma_gemm_kernel<128, 256, 128, 0>,
                             cudaFuncAttributeMaxDynamicSharedMemorySize, SM_FC1);
        attr_set = 1;
    }

    const int NB = (N_NODES + 127) / 128;

    detect_idx_kernel<<<1, 32>>>(idxw);
    conv_idx_kernel<<<(N_NODES * SEQ + 255) / 256, 256>>>(idxw);
    split_kernel<<<(64 * 512 + 255) / 256, 256>>>(w2, w2h, w2l, 64 * 512);
    split_kernel<<<(128 * 1024 + 255) / 256, 256>>>(w3, w3h, w3l, 128 * 1024);
    split_kernel<<<(256 * 128 + 255) / 256, 256>>>(fc1_w, f1h, f1l, 256 * 128);
    fc0_kernel<<<(N_NODES + 255) / 256, 256>>>(x, fc0_w, fc0_b);

    // spiral conv 1: C=16, K=256, O=32 (FFMA2)
    gemm_elu_kernel<16, 256, 32, 128, 32, 4, 4, true>
        <<<dim3(NB, 1), 256>>>(h0, h1, w1, b1);
    // spiral conv 2: C=32, K=512, O=64 (warp MMA)
    mma_gemm_kernel<512, 64, 64, 32>
        <<<dim3(NB, 1), 256, SM_L2>>>(h1, h2, w2h, w2l, b2);
    // spiral conv 3: C=64, K=1024, O=128 (warp MMA)
    mma_gemm_kernel<1024, 128, 128, 64>
        <<<dim3(NB, 1), 256, SM_L3>>>(h2, h3, w3h, w3l, b3);
    // fc1 dense: K=128, O=256 (warp MMA, 2 output tiles)
    mma_gemm_kernel<128, 256, 128, 0>
        <<<dim3(NB, 2), 256, SM_FC1>>>(h3, h4, f1h, f1l, fc1_b);
    // fc2 + log_softmax
    fc2_lsm_kernel<<<(N_NODES + 7) / 8, 256>>>(fc2_w, fc2_b, out);
}

// round 7
// speedup vs baseline: 2.4946x; 1.1540x over previous
#include <cuda_runtime.h>
#include <cuda_bf16.h>
#include <math.h>
#include <stdint.h>

#define N_NODES 100000
#define SEQ 16

// Scratch activations as bf16 hi/lo pairs (device globals: no allocation).
__device__ __align__(16) __nv_bfloat16 g_h0h[N_NODES * 16];
__device__ __align__(16) __nv_bfloat16 g_h0l[N_NODES * 16];
__device__ __align__(16) __nv_bfloat16 g_h1h[N_NODES * 32];
__device__ __align__(16) __nv_bfloat16 g_h1l[N_NODES * 32];
__device__ __align__(16) __nv_bfloat16 g_h2h[N_NODES * 64];
__device__ __align__(16) __nv_bfloat16 g_h2l[N_NODES * 64];
__device__ __align__(16) __nv_bfloat16 g_h3h[N_NODES * 128];
__device__ __align__(16) __nv_bfloat16 g_h3l[N_NODES * 128];
__device__ __align__(16) float g_h4[N_NODES * 256];
__device__ int g_idx[N_NODES * SEQ];
__device__ int g_is64;
// weights split into bf16 hi/lo (prepared once per launch)
__device__ __align__(16) __nv_bfloat16 g_w1h[32 * 256];
__device__ __align__(16) __nv_bfloat16 g_w1l[32 * 256];
__device__ __align__(16) __nv_bfloat16 g_w2h[64 * 512];
__device__ __align__(16) __nv_bfloat16 g_w2l[64 * 512];
__device__ __align__(16) __nv_bfloat16 g_w3h[128 * 1024];
__device__ __align__(16) __nv_bfloat16 g_w3l[128 * 1024];
__device__ __align__(16) __nv_bfloat16 g_f1h[256 * 128];
__device__ __align__(16) __nv_bfloat16 g_f1l[256 * 128];

__device__ __forceinline__ float elu(float v) {
    return v > 0.f ? v : expm1f(v);
}

// ---------------- helpers ----------------
__device__ __forceinline__ uint32_t smem_to_u32(const void* p) {
    uint32_t a;
    asm("{ .reg .u64 tmp; cvta.to.shared.u64 tmp, %1; cvt.u32.u64 %0, tmp; }"
        : "=r"(a) : "l"(p));
    return a;
}
#define SWZ(b) ((b) ^ (((b) >> 3) & 0x70))

__device__ __forceinline__ void ldsm_x4(uint32_t* r, uint32_t addr) {
    asm volatile(
        "ldmatrix.sync.aligned.m8n8.x4.shared.b16 {%0,%1,%2,%3}, [%4];"
        : "=r"(r[0]), "=r"(r[1]), "=r"(r[2]), "=r"(r[3]) : "r"(addr));
}
__device__ __forceinline__ void mma_bf16(float* c, const uint32_t* a,
                                         uint32_t b0, uint32_t b1) {
    asm volatile(
        "mma.sync.aligned.m16n8k16.row.col.f32.bf16.bf16.f32 "
        "{%0,%1,%2,%3}, {%4,%5,%6,%7}, {%8,%9}, {%0,%1,%2,%3};"
        : "+f"(c[0]), "+f"(c[1]), "+f"(c[2]), "+f"(c[3])
        : "r"(a[0]), "r"(a[1]), "r"(a[2]), "r"(a[3]), "r"(b0), "r"(b1));
}
__device__ __forceinline__ void cp16(uint32_t dst, const void* src) {
    asm volatile("cp.async.ca.shared.global [%0], [%1], 16;"
                 :: "r"(dst), "l"(src));
}
#define CP_COMMIT() asm volatile("cp.async.commit_group;" ::: "memory")
#define CP_WAIT0()  asm volatile("cp.async.wait_group 0;" ::: "memory")

__device__ __forceinline__ uint32_t pack_hi2(float a, float b,
                                             float& la, float& lb) {
    __nv_bfloat162 h = __floats2bfloat162_rn(a, b);
    la = a - __bfloat162float(__low2bfloat16(h));
    lb = b - __bfloat162float(__high2bfloat16(h));
    return *reinterpret_cast<uint32_t*>(&h);
}
__device__ __forceinline__ uint32_t pack_lo2(float a, float b) {
    __nv_bfloat162 l = __floats2bfloat162_rn(a, b);
    return *reinterpret_cast<uint32_t*>(&l);
}

// ---------------------------------------------------------------------------
// Index dtype detection + conversion (reference declares int64; JAX default
// x64-off actually yields int32 — detect on device, clamp for safety).
// ---------------------------------------------------------------------------
__global__ void detect_idx_kernel(const int* __restrict__ w32) {
    if (threadIdx.x == 0) {
        int all_zero = 1;
        for (int k = 0; k < 64; k++) {
            if (w32[2 * k * 1024 + 1] != 0) { all_zero = 0; break; }
        }
        g_is64 = all_zero;
    }
}
__global__ void conv_idx_kernel(const int* __restrict__ w32) {
    int i = blockIdx.x * blockDim.x + threadIdx.x;
    if (i >= N_NODES * SEQ) return;
    int v = g_is64 ? w32[2 * i] : w32[i];
    if (v < 0) v = 0;
    if (v >= N_NODES) v = N_NODES - 1;
    g_idx[i] = v;
}

// ---------------------------------------------------------------------------
// fp32 -> bf16 hi/lo weight split
// ---------------------------------------------------------------------------
__global__ void split_kernel(const float* __restrict__ w,
                             __nv_bfloat16* __restrict__ hi,
                             __nv_bfloat16* __restrict__ lo, int n) {
    int i = blockIdx.x * blockDim.x + threadIdx.x;
    if (i >= n) return;
    float v = w[i];
    __nv_bfloat16 h = __float2bfloat16(v);
    hi[i] = h;
    lo[i] = __float2bfloat16(v - __bfloat162float(h));
}

// ---------------------------------------------------------------------------
// fc0: [N,3] @ [3,16]^T + b, ELU -> bf16 hi/lo split output.
// ---------------------------------------------------------------------------
__global__ __launch_bounds__(256) void fc0_kernel(
    const float* __restrict__ x,
    const float* __restrict__ w,
    const float* __restrict__ bias)
{
    __shared__ float sw[48];
    __shared__ float sb[16];
    if (threadIdx.x < 48) sw[threadIdx.x] = w[threadIdx.x];
    if (threadIdx.x < 16) sb[threadIdx.x] = bias[threadIdx.x];
    __syncthreads();

    int n = blockIdx.x * blockDim.x + threadIdx.x;
    if (n >= N_NODES) return;

    float x0 = x[n * 3 + 0], x1 = x[n * 3 + 1], x2 = x[n * 3 + 2];
    uint32_t hi[8], lo[8];
#pragma unroll
    for (int j = 0; j < 8; j++) {
        float v0 = sb[2 * j] + sw[(2 * j) * 3] * x0 + sw[(2 * j) * 3 + 1] * x1 +
                   sw[(2 * j) * 3 + 2] * x2;
        float v1 = sb[2 * j + 1] + sw[(2 * j + 1) * 3] * x0 +
                   sw[(2 * j + 1) * 3 + 1] * x1 + sw[(2 * j + 1) * 3 + 2] * x2;
        v0 = elu(v0); v1 = elu(v1);
        float l0, l1;
        hi[j] = pack_hi2(v0, v1, l0, l1);
        lo[j] = pack_lo2(l0, l1);
    }
    uint4* dh = reinterpret_cast<uint4*>(g_h0h + (size_t)n * 16);
    uint4* dl = reinterpret_cast<uint4*>(g_h0l + (size_t)n * 16);
    dh[0] = make_uint4(hi[0], hi[1], hi[2], hi[3]);
    dh[1] = make_uint4(hi[4], hi[5], hi[6], hi[7]);
    dl[0] = make_uint4(lo[0], lo[1], lo[2], lo[3]);
    dl[1] = make_uint4(lo[4], lo[5], lo[6], lo[7]);
}

// ---------------------------------------------------------------------------
// Warp-MMA gathered GEMM: bf16 hi/lo inputs (pre-split), fp32 accum,
// 3 terms Ahi*Whi + Ahi*Wlo + Alo*Whi.
// BM=128 nodes x OT outputs per block; BK=64 bf16 k-slab; 8 warps (4x2),
// warp tile 32 x WN. cp.async 16B gather-copy into swizzled smem,
// double-buffered, one __syncthreads per slab.
// C: input channels per neighbor (0 = dense).
// ---------------------------------------------------------------------------
template <int K, int OTOT, int OT, int C, bool SPLIT>
__global__ __launch_bounds__(256, 1) void mma_gemm_kernel(
    const __nv_bfloat16* __restrict__ ph,
    const __nv_bfloat16* __restrict__ pl,
    const __nv_bfloat16* __restrict__ wh,
    const __nv_bfloat16* __restrict__ wl,
    const float* __restrict__ bias,
    float* __restrict__ outf,
    __nv_bfloat16* __restrict__ oh,
    __nv_bfloat16* __restrict__ ol)
{
    constexpr int NSLAB  = K / 64;
    constexpr int WN     = OT / 2;
    constexpr int NT     = WN / 8;
    constexpr int NT2    = WN / 16;
    constexpr int ACH    = 8;                 // A 16B chunks / thread
    constexpr int BCH    = OT * 16 / 256;     // B 16B chunks / thread
    constexpr uint32_t ABYTES = 128 * 128;    // per part
    constexpr uint32_t BBYTES = OT * 128;
    constexpr uint32_t BUF    = 2 * ABYTES + 2 * BBYTES;

    extern __shared__ char smem[];
    const uint32_t sbu = smem_to_u32(smem);
    int* sIdx = reinterpret_cast<int*>(smem + 2 * BUF);

    const int t    = threadIdx.x;
    const int wid  = t >> 5;
    const int lane = t & 31;
    const int wm   = wid & 3;
    const int wn   = wid >> 2;
    const int gid  = lane >> 2;
    const int tid  = lane & 3;
    const int n0   = blockIdx.x * 128;
    const int o_off = blockIdx.y * OT;

    if constexpr (C > 0) {
        for (int i = t; i < 128 * SEQ; i += 256) {
            int node = n0 + (i >> 4);
            if (node > N_NODES - 1) node = N_NODES - 1;
            sIdx[i] = g_idx[node * SEQ + (i & 15)];
        }
        __syncthreads();
    }

    auto issue_copy = [&](int s, int buf) {
        uint32_t base = sbu + buf * BUF;
#pragma unroll
        for (int j = 0; j < ACH; j++) {
            int id   = t + 256 * j;
            int row  = id >> 4;
            int cc   = id & 15;
            int part = cc >> 3;
            int c    = cc & 7;
            int kg   = s * 64 + c * 8;
            const __nv_bfloat16* src;
            if constexpr (C == 0) {
                int node = n0 + row;
                if (node > N_NODES - 1) node = N_NODES - 1;
                src = (part ? pl : ph) + (size_t)node * K + kg;
            } else {
                int sn = sIdx[row * SEQ + kg / C];
                src = (part ? pl : ph) + (size_t)sn * C + (kg % C);
            }
            uint32_t dst = base + part * ABYTES +
                           SWZ((uint32_t)(row * 128 + c * 16));
            cp16(dst, src);
        }
#pragma unroll
        for (int j = 0; j < BCH; j++) {
            int id   = t + 256 * j;
            int o    = id >> 4;
            int cc   = id & 15;
            int part = cc >> 3;
            int c    = cc & 7;
            const __nv_bfloat16* src =
                (part ? wl : wh) + (size_t)(o_off + o) * K + s * 64 + c * 8;
            uint32_t dst = base + 2 * ABYTES + part * BBYTES +
                           SWZ((uint32_t)(o * 128 + c * 16));
            cp16(dst, src);
        }
        CP_COMMIT();
    };

    float acc[2][NT][4];
#pragma unroll
    for (int m = 0; m < 2; m++)
#pragma unroll
        for (int n = 0; n < NT; n++)
#pragma unroll
            for (int q = 0; q < 4; q++) acc[m][n][q] = 0.f;

    issue_copy(0, 0);
    CP_WAIT0();
    __syncthreads();

    const uint32_t flrow  = lane & 15;
    const uint32_t fchalf = (lane >> 4) * 16;

    int buf = 0;
    for (int s = 0; s < NSLAB; s++) {
        if (s + 1 < NSLAB) issue_copy(s + 1, buf ^ 1);

        uint32_t base = sbu + buf * BUF;
#pragma unroll
        for (int kc = 0; kc < 4; kc++) {
            uint32_t colb = kc * 32 + fchalf;
            uint32_t ah[2][4], al[2][4];
#pragma unroll
            for (int mt = 0; mt < 2; mt++) {
                uint32_t off = (wm * 32 + mt * 16 + flrow) * 128 + colb;
                uint32_t sw  = SWZ(off);
                ldsm_x4(ah[mt], base + sw);
                ldsm_x4(al[mt], base + ABYTES + sw);
            }
#pragma unroll
            for (int n2 = 0; n2 < NT2; n2++) {
                uint32_t off = (wn * WN + n2 * 16 + flrow) * 128 + colb;
                uint32_t sw  = SWZ(off);
                uint32_t fh[4], fl[4];
                ldsm_x4(fh, base + 2 * ABYTES + sw);
                ldsm_x4(fl, base + 2 * ABYTES + BBYTES + sw);
#pragma unroll
                for (int mt = 0; mt < 2; mt++) {
                    mma_bf16(acc[mt][n2 * 2],     ah[mt], fh[0], fh[2]);
                    mma_bf16(acc[mt][n2 * 2],     ah[mt], fl[0], fl[2]);
                    mma_bf16(acc[mt][n2 * 2],     al[mt], fh[0], fh[2]);
                    mma_bf16(acc[mt][n2 * 2 + 1], ah[mt], fh[1], fh[3]);
                    mma_bf16(acc[mt][n2 * 2 + 1], ah[mt], fl[1], fl[3]);
                    mma_bf16(acc[mt][n2 * 2 + 1], al[mt], fh[1], fh[3]);
                }
            }
        }

        if (s + 1 < NSLAB) CP_WAIT0();
        __syncthreads();
        buf ^= 1;
    }

    // ---- epilogue: bias + ELU; fp32 or bf16 hi/lo split output ----
#pragma unroll
    for (int mt = 0; mt < 2; mt++) {
#pragma unroll
        for (int nt = 0; nt < NT; nt++) {
            int col = o_off + wn * WN + nt * 8 + tid * 2;
            float b0 = bias[col], b1 = bias[col + 1];
            int r0 = n0 + wm * 32 + mt * 16 + gid;
            int r1 = r0 + 8;
            float v0 = elu(acc[mt][nt][0] + b0);
            float v1 = elu(acc[mt][nt][1] + b1);
            float v2 = elu(acc[mt][nt][2] + b0);
            float v3 = elu(acc[mt][nt][3] + b1);
            if constexpr (SPLIT) {
                if (r0 < N_NODES) {
                    float l0, l1;
                    uint32_t h = pack_hi2(v0, v1, l0, l1);
                    *reinterpret_cast<uint32_t*>(oh + (size_t)r0 * OTOT + col) = h;
                    *reinterpret_cast<uint32_t*>(ol + (size_t)r0 * OTOT + col) =
                        pack_lo2(l0, l1);
                }
                if (r1 < N_NODES) {
                    float l0, l1;
                    uint32_t h = pack_hi2(v2, v3, l0, l1);
                    *reinterpret_cast<uint32_t*>(oh + (size_t)r1 * OTOT + col) = h;
                    *reinterpret_cast<uint32_t*>(ol + (size_t)r1 * OTOT + col) =
                        pack_lo2(l0, l1);
                }
            } else {
                if (r0 < N_NODES) {
                    float2 v; v.x = v0; v.y = v1;
                    *reinterpret_cast<float2*>(outf + (size_t)r0 * OTOT + col) = v;
                }
                if (r1 < N_NODES) {
                    float2 v; v.x = v2; v.y = v3;
                    *reinterpret_cast<float2*>(outf + (size_t)r1 * OTOT + col) = v;
                }
            }
        }
    }
}

// ---------------------------------------------------------------------------
// fc2 + log_softmax: one warp per node. 12 outputs from 256 inputs.
// ---------------------------------------------------------------------------
__global__ __launch_bounds__(256) void fc2_lsm_kernel(
    const float* __restrict__ w,
    const float* __restrict__ bias,
    float* __restrict__ out)
{
    __shared__ float sw[12][256];
    __shared__ float sb[12];
    int t = threadIdx.x;
    for (int i = t; i < 12 * 256; i += 256) sw[i >> 8][i & 255] = w[i];
    if (t < 12) sb[t] = bias[t];
    __syncthreads();

    int node = blockIdx.x * 8 + (t >> 5);
    int lane = t & 31;
    if (node >= N_NODES) return;

    const float* row = g_h4 + (size_t)node * 256;
    float acc[12];
#pragma unroll
    for (int o = 0; o < 12; o++) acc[o] = 0.f;

#pragma unroll
    for (int r = 0; r < 8; r++) {
        float hv = row[lane + 32 * r];
#pragma unroll
        for (int o = 0; o < 12; o++) acc[o] += hv * sw[o][lane + 32 * r];
    }

#pragma unroll
    for (int o = 0; o < 12; o++) {
#pragma unroll
        for (int d = 16; d > 0; d >>= 1)
            acc[o] += __shfl_xor_sync(0xffffffffu, acc[o], d);
        acc[o] += sb[o];
    }

    float m = acc[0];
#pragma unroll
    for (int o = 1; o < 12; o++) m = fmaxf(m, acc[o]);
    float s = 0.f;
#pragma unroll
    for (int o = 0; o < 12; o++) s += expf(acc[o] - m);
    float lse = m + logf(s);

    if (lane < 12) out[(size_t)node * 12 + lane] = acc[lane] - lse;
}

// ---------------------------------------------------------------------------
// Launch
// ---------------------------------------------------------------------------
extern "C" void kernel_launch(void* const* d_in, const int* in_sizes, int n_in,
                              void* d_out, int out_size)
{
    const float* x      = (const float*)d_in[0];
    const int*   idxw   = (const int*)d_in[1];
    const float* fc0_w  = (const float*)d_in[2];
    const float* fc0_b  = (const float*)d_in[3];
    const float* w1     = (const float*)d_in[4];
    const float* b1     = (const float*)d_in[5];
    const float* w2     = (const float*)d_in[6];
    const float* b2     = (const float*)d_in[7];
    const float* w3     = (const float*)d_in[8];
    const float* b3     = (const float*)d_in[9];
    const float* fc1_w  = (const float*)d_in[10];
    const float* fc1_b  = (const float*)d_in[11];
    const float* fc2_w  = (const float*)d_in[12];
    const float* fc2_b  = (const float*)d_in[13];
    float* out = (float*)d_out;

    __nv_bfloat16 *h0h, *h0l, *h1h, *h1l, *h2h, *h2l, *h3h, *h3l;
    float* h4;
    cudaGetSymbolAddress((void**)&h0h, g_h0h);
    cudaGetSymbolAddress((void**)&h0l, g_h0l);
    cudaGetSymbolAddress((void**)&h1h, g_h1h);
    cudaGetSymbolAddress((void**)&h1l, g_h1l);
    cudaGetSymbolAddress((void**)&h2h, g_h2h);
    cudaGetSymbolAddress((void**)&h2l, g_h2l);
    cudaGetSymbolAddress((void**)&h3h, g_h3h);
    cudaGetSymbolAddress((void**)&h3l, g_h3l);
    cudaGetSymbolAddress((void**)&h4, g_h4);

    __nv_bfloat16 *w1h, *w1l, *w2h, *w2l, *w3h, *w3l, *f1h, *f1l;
    cudaGetSymbolAddress((void**)&w1h, g_w1h);
    cudaGetSymbolAddress((void**)&w1l, g_w1l);
    cudaGetSymbolAddress((void**)&w2h, g_w2h);
    cudaGetSymbolAddress((void**)&w2l, g_w2l);
    cudaGetSymbolAddress((void**)&w3h, g_w3h);
    cudaGetSymbolAddress((void**)&w3l, g_w3l);
    cudaGetSymbolAddress((void**)&f1h, g_f1h);
    cudaGetSymbolAddress((void**)&f1l, g_f1l);

    // dynamic smem: 2 * (2*16K A + 2*OT*128 B) + 8K idx
    const int SM_L1  = 2 * (32768 + 2 * 32 * 128) + 8192;    //  90112
    const int SM_L2  = 2 * (32768 + 2 * 64 * 128) + 8192;    // 106496
    const int SM_L3  = 2 * (32768 + 2 * 128 * 128) + 8192;   // 139264
    const int SM_FC1 = SM_L3;

    static int attr_set = 0;
    if (!attr_set) {
        cudaFuncSetAttribute(mma_gemm_kernel<256, 32, 32, 16, true>,
                             cudaFuncAttributeMaxDynamicSharedMemorySize, SM_L1);
        cudaFuncSetAttribute(mma_gemm_kernel<512, 64, 64, 32, true>,
                             cudaFuncAttributeMaxDynamicSharedMemorySize, SM_L2);
        cudaFuncSetAttribute(mma_gemm_kernel<1024, 128, 128, 64, true>,
                             cudaFuncAttributeMaxDynamicSharedMemorySize, SM_L3);
        cudaFuncSetAttribute(mma_gemm_kernel<128, 256, 128, 0, false>,
                             cudaFuncAttributeMaxDynamicSharedMemorySize, SM_FC1);
        attr_set = 1;
    }

    const int NB = (N_NODES + 127) / 128;

    detect_idx_kernel<<<1, 32>>>(idxw);
    conv_idx_kernel<<<(N_NODES * SEQ + 255) / 256, 256>>>(idxw);
    split_kernel<<<(32 * 256 + 255) / 256, 256>>>(w1, w1h, w1l, 32 * 256);
    split_kernel<<<(64 * 512 + 255) / 256, 256>>>(w2, w2h, w2l, 64 * 512);
    split_kernel<<<(128 * 1024 + 255) / 256, 256>>>(w3, w3h, w3l, 128 * 1024);
    split_kernel<<<(256 * 128 + 255) / 256, 256>>>(fc1_w, f1h, f1l, 256 * 128);
    fc0_kernel<<<(N_NODES + 255) / 256, 256>>>(x, fc0_w, fc0_b);

    // spiral conv 1: C=16, K=256, O=32
    mma_gemm_kernel<256, 32, 32, 16, true><<<dim3(NB, 1), 256, SM_L1>>>(
        h0h, h0l, w1h, w1l, b1, nullptr, h1h, h1l);
    // spiral conv 2: C=32, K=512, O=64
    mma_gemm_kernel<512, 64, 64, 32, true><<<dim3(NB, 1), 256, SM_L2>>>(
        h1h, h1l, w2h, w2l, b2, nullptr, h2h, h2l);
    // spiral conv 3: C=64, K=1024, O=128
    mma_gemm_kernel<1024, 128, 128, 64, true><<<dim3(NB, 1), 256, SM_L3>>>(
        h2h, h2l, w3h, w3l, b3, nullptr, h3h, h3l);
    // fc1 dense: K=128, O=256 (2 output tiles)
    mma_gemm_kernel<128, 256, 128, 0, false><<<dim3(NB, 2), 256, SM_FC1>>>(
        h3h, h3l, f1h, f1l, fc1_b, h4, nullptr, nullptr);
    // fc2 + log_softmax
    fc2_lsm_kernel<<<(N_NODES + 7) / 8, 256>>>(fc2_w, fc2_b, out);
}

// round 8
// speedup vs baseline: 2.6143x; 1.0480x over previous
#include <cuda_runtime.h>
#include <cuda_bf16.h>
#include <math.h>
#include <stdint.h>

#define N_NODES 100000
#define SEQ 16

// Scratch activations as bf16 hi/lo pairs (device globals: no allocation).
__device__ __align__(16) __nv_bfloat16 g_h0h[N_NODES * 16];
__device__ __align__(16) __nv_bfloat16 g_h0l[N_NODES * 16];
__device__ __align__(16) __nv_bfloat16 g_h1h[N_NODES * 32];
__device__ __align__(16) __nv_bfloat16 g_h1l[N_NODES * 32];
__device__ __align__(16) __nv_bfloat16 g_h2h[N_NODES * 64];
__device__ __align__(16) __nv_bfloat16 g_h2l[N_NODES * 64];
__device__ __align__(16) __nv_bfloat16 g_h3h[N_NODES * 128];
__device__ __align__(16) __nv_bfloat16 g_h3l[N_NODES * 128];
__device__ __align__(16) float g_h4[N_NODES * 256];
__device__ int g_idx[N_NODES * SEQ];
__device__ int g_is64;
// weights split into bf16 hi/lo (prepared once per launch)
__device__ __align__(16) __nv_bfloat16 g_w1h[32 * 256];
__device__ __align__(16) __nv_bfloat16 g_w1l[32 * 256];
__device__ __align__(16) __nv_bfloat16 g_w2h[64 * 512];
__device__ __align__(16) __nv_bfloat16 g_w2l[64 * 512];
__device__ __align__(16) __nv_bfloat16 g_w3h[128 * 1024];
__device__ __align__(16) __nv_bfloat16 g_w3l[128 * 1024];
__device__ __align__(16) __nv_bfloat16 g_f1h[256 * 128];
__device__ __align__(16) __nv_bfloat16 g_f1l[256 * 128];

__device__ __forceinline__ float elu(float v) {
    return v > 0.f ? v : expm1f(v);
}

// ---------------- helpers ----------------
__device__ __forceinline__ uint32_t smem_to_u32(const void* p) {
    uint32_t a;
    asm("{ .reg .u64 tmp; cvta.to.shared.u64 tmp, %1; cvt.u32.u64 %0, tmp; }"
        : "=r"(a) : "l"(p));
    return a;
}
#define SWZ(b) ((b) ^ (((b) >> 3) & 0x70))

__device__ __forceinline__ void ldsm_x4(uint32_t* r, uint32_t addr) {
    asm volatile(
        "ldmatrix.sync.aligned.m8n8.x4.shared.b16 {%0,%1,%2,%3}, [%4];"
        : "=r"(r[0]), "=r"(r[1]), "=r"(r[2]), "=r"(r[3]) : "r"(addr));
}
__device__ __forceinline__ void mma_bf16(float* c, const uint32_t* a,
                                         uint32_t b0, uint32_t b1) {
    asm volatile(
        "mma.sync.aligned.m16n8k16.row.col.f32.bf16.bf16.f32 "
        "{%0,%1,%2,%3}, {%4,%5,%6,%7}, {%8,%9}, {%0,%1,%2,%3};"
        : "+f"(c[0]), "+f"(c[1]), "+f"(c[2]), "+f"(c[3])
        : "r"(a[0]), "r"(a[1]), "r"(a[2]), "r"(a[3]), "r"(b0), "r"(b1));
}
__device__ __forceinline__ void cp16(uint32_t dst, const void* src) {
    asm volatile("cp.async.ca.shared.global [%0], [%1], 16;"
                 :: "r"(dst), "l"(src));
}
#define CP_COMMIT() asm volatile("cp.async.commit_group;" ::: "memory")
#define CP_WAIT0()  asm volatile("cp.async.wait_group 0;" ::: "memory")

__device__ __forceinline__ uint32_t pack_hi2(float a, float b,
                                             float& la, float& lb) {
    __nv_bfloat162 h = __floats2bfloat162_rn(a, b);
    la = a - __bfloat162float(__low2bfloat16(h));
    lb = b - __bfloat162float(__high2bfloat16(h));
    return *reinterpret_cast<uint32_t*>(&h);
}
__device__ __forceinline__ uint32_t pack_lo2(float a, float b) {
    __nv_bfloat162 l = __floats2bfloat162_rn(a, b);
    return *reinterpret_cast<uint32_t*>(&l);
}

// ---------------------------------------------------------------------------
// Index dtype detection + conversion (reference declares int64; JAX default
// x64-off actually yields int32 — detect on device, clamp for safety).
// ---------------------------------------------------------------------------
__global__ void detect_idx_kernel(const int* __restrict__ w32) {
    if (threadIdx.x == 0) {
        int all_zero = 1;
        for (int k = 0; k < 64; k++) {
            if (w32[2 * k * 1024 + 1] != 0) { all_zero = 0; break; }
        }
        g_is64 = all_zero;
    }
}
__global__ void conv_idx_kernel(const int* __restrict__ w32) {
    int i = blockIdx.x * blockDim.x + threadIdx.x;
    if (i >= N_NODES * SEQ) return;
    int v = g_is64 ? w32[2 * i] : w32[i];
    if (v < 0) v = 0;
    if (v >= N_NODES) v = N_NODES - 1;
    g_idx[i] = v;
}

// ---------------------------------------------------------------------------
// All four weight splits in one kernel (also keeps ncu's -s 5 on an MMA
// kernel instead of a prep kernel).
// ---------------------------------------------------------------------------
__global__ void split_all_kernel(const float* __restrict__ w1,
                                 const float* __restrict__ w2,
                                 const float* __restrict__ w3,
                                 const float* __restrict__ f1) {
    int i = blockIdx.x * blockDim.x + threadIdx.x;
    const float* src;
    __nv_bfloat16 *hi, *lo;
    int off;
    if (i < 8192)              { src = w1; hi = g_w1h; lo = g_w1l; off = i; }
    else if (i < 8192 + 32768) { src = w2; hi = g_w2h; lo = g_w2l; off = i - 8192; }
    else if (i < 8192 + 32768 + 131072) {
        src = w3; hi = g_w3h; lo = g_w3l; off = i - 8192 - 32768;
    } else if (i < 8192 + 32768 + 131072 + 32768) {
        src = f1; hi = g_f1h; lo = g_f1l; off = i - 8192 - 32768 - 131072;
    } else return;
    float v = src[off];
    __nv_bfloat16 h = __float2bfloat16(v);
    hi[off] = h;
    lo[off] = __float2bfloat16(v - __bfloat162float(h));
}

// ---------------------------------------------------------------------------
// fc0: [N,3] @ [3,16]^T + b, ELU -> bf16 hi/lo split output.
// ---------------------------------------------------------------------------
__global__ __launch_bounds__(256) void fc0_kernel(
    const float* __restrict__ x,
    const float* __restrict__ w,
    const float* __restrict__ bias)
{
    __shared__ float sw[48];
    __shared__ float sb[16];
    if (threadIdx.x < 48) sw[threadIdx.x] = w[threadIdx.x];
    if (threadIdx.x < 16) sb[threadIdx.x] = bias[threadIdx.x];
    __syncthreads();

    int n = blockIdx.x * blockDim.x + threadIdx.x;
    if (n >= N_NODES) return;

    float x0 = x[n * 3 + 0], x1 = x[n * 3 + 1], x2 = x[n * 3 + 2];
    uint32_t hi[8], lo[8];
#pragma unroll
    for (int j = 0; j < 8; j++) {
        float v0 = sb[2 * j] + sw[(2 * j) * 3] * x0 + sw[(2 * j) * 3 + 1] * x1 +
                   sw[(2 * j) * 3 + 2] * x2;
        float v1 = sb[2 * j + 1] + sw[(2 * j + 1) * 3] * x0 +
                   sw[(2 * j + 1) * 3 + 1] * x1 + sw[(2 * j + 1) * 3 + 2] * x2;
        v0 = elu(v0); v1 = elu(v1);
        float l0, l1;
        hi[j] = pack_hi2(v0, v1, l0, l1);
        lo[j] = pack_lo2(l0, l1);
    }
    uint4* dh = reinterpret_cast<uint4*>(g_h0h + (size_t)n * 16);
    uint4* dl = reinterpret_cast<uint4*>(g_h0l + (size_t)n * 16);
    dh[0] = make_uint4(hi[0], hi[1], hi[2], hi[3]);
    dh[1] = make_uint4(hi[4], hi[5], hi[6], hi[7]);
    dl[0] = make_uint4(lo[0], lo[1], lo[2], lo[3]);
    dl[1] = make_uint4(lo[4], lo[5], lo[6], lo[7]);
}

// ---------------------------------------------------------------------------
// Warp-MMA gathered GEMM: bf16 hi/lo inputs (pre-split), fp32 accum,
// 3 terms Ahi*Whi + Ahi*Wlo + Alo*Whi.
// BM=256 nodes x OT outputs per block, 512 threads (16 warps as 8x2,
// warp tile 32 x WN). BK=64 bf16 k-slab; cp.async 16B gather-copy into
// swizzled smem, double-buffered, one __syncthreads per slab.
// C: input channels per neighbor (0 = dense).
// ---------------------------------------------------------------------------
template <int K, int OTOT, int OT, int C, bool SPLIT>
__global__ __launch_bounds__(512, 1) void mma_gemm_kernel(
    const __nv_bfloat16* __restrict__ ph,
    const __nv_bfloat16* __restrict__ pl,
    const __nv_bfloat16* __restrict__ wh,
    const __nv_bfloat16* __restrict__ wl,
    const float* __restrict__ bias,
    float* __restrict__ outf,
    __nv_bfloat16* __restrict__ oh,
    __nv_bfloat16* __restrict__ ol)
{
    constexpr int BM     = 256;
    constexpr int NSLAB  = K / 64;
    constexpr int WN     = OT / 2;
    constexpr int NT     = WN / 8;
    constexpr int NT2    = WN / 16;
    constexpr int ACH    = BM * 16 / 512;     // A 16B chunks / thread
    constexpr int BCH    = OT * 16 / 512;     // B 16B chunks / thread
    constexpr uint32_t ABYTES = BM * 128;     // per part (32 KB)
    constexpr uint32_t BBYTES = OT * 128;
    constexpr uint32_t BUF    = 2 * ABYTES + 2 * BBYTES;

    extern __shared__ char smem[];
    const uint32_t sbu = smem_to_u32(smem);
    int* sIdx = reinterpret_cast<int*>(smem + 2 * BUF);

    const int t    = threadIdx.x;
    const int wid  = t >> 5;
    const int lane = t & 31;
    const int wm   = wid & 7;        // 8 warps along M
    const int wn   = wid >> 3;       // 2 warps along N
    const int gid  = lane >> 2;
    const int tid  = lane & 3;
    const int n0   = blockIdx.x * BM;
    const int o_off = blockIdx.y * OT;

    if constexpr (C > 0) {
        for (int i = t; i < BM * SEQ; i += 512) {
            int node = n0 + (i >> 4);
            if (node > N_NODES - 1) node = N_NODES - 1;
            sIdx[i] = g_idx[node * SEQ + (i & 15)];
        }
        __syncthreads();
    }

    auto issue_copy = [&](int s, int buf) {
        uint32_t base = sbu + buf * BUF;
#pragma unroll
        for (int j = 0; j < ACH; j++) {
            int id   = t + 512 * j;
            int row  = id >> 4;
            int cc   = id & 15;
            int part = cc >> 3;
            int c    = cc & 7;
            int kg   = s * 64 + c * 8;
            const __nv_bfloat16* src;
            if constexpr (C == 0) {
                int node = n0 + row;
                if (node > N_NODES - 1) node = N_NODES - 1;
                src = (part ? pl : ph) + (size_t)node * K + kg;
            } else {
                int sn = sIdx[row * SEQ + kg / C];
                src = (part ? pl : ph) + (size_t)sn * C + (kg % C);
            }
            uint32_t dst = base + part * ABYTES +
                           SWZ((uint32_t)(row * 128 + c * 16));
            cp16(dst, src);
        }
#pragma unroll
        for (int j = 0; j < BCH; j++) {
            int id   = t + 512 * j;
            int o    = id >> 4;
            int cc   = id & 15;
            int part = cc >> 3;
            int c    = cc & 7;
            const __nv_bfloat16* src =
                (part ? wl : wh) + (size_t)(o_off + o) * K + s * 64 + c * 8;
            uint32_t dst = base + 2 * ABYTES + part * BBYTES +
                           SWZ((uint32_t)(o * 128 + c * 16));
            cp16(dst, src);
        }
        CP_COMMIT();
    };

    float acc[2][NT][4];
#pragma unroll
    for (int m = 0; m < 2; m++)
#pragma unroll
        for (int n = 0; n < NT; n++)
#pragma unroll
            for (int q = 0; q < 4; q++) acc[m][n][q] = 0.f;

    issue_copy(0, 0);
    CP_WAIT0();
    __syncthreads();

    const uint32_t flrow  = lane & 15;
    const uint32_t fchalf = (lane >> 4) * 16;

    int buf = 0;
    for (int s = 0; s < NSLAB; s++) {
        if (s + 1 < NSLAB) issue_copy(s + 1, buf ^ 1);

        uint32_t base = sbu + buf * BUF;
#pragma unroll
        for (int kc = 0; kc < 4; kc++) {
            uint32_t colb = kc * 32 + fchalf;
            uint32_t ah[2][4], al[2][4];
#pragma unroll
            for (int mt = 0; mt < 2; mt++) {
                uint32_t off = (wm * 32 + mt * 16 + flrow) * 128 + colb;
                uint32_t sw  = SWZ(off);
                ldsm_x4(ah[mt], base + sw);
                ldsm_x4(al[mt], base + ABYTES + sw);
            }
#pragma unroll
            for (int n2 = 0; n2 < NT2; n2++) {
                uint32_t off = (wn * WN + n2 * 16 + flrow) * 128 + colb;
                uint32_t sw  = SWZ(off);
                uint32_t fh[4], fl[4];
                ldsm_x4(fh, base + 2 * ABYTES + sw);
                ldsm_x4(fl, base + 2 * ABYTES + BBYTES + sw);
#pragma unroll
                for (int mt = 0; mt < 2; mt++) {
                    mma_bf16(acc[mt][n2 * 2],     ah[mt], fh[0], fh[2]);
                    mma_bf16(acc[mt][n2 * 2 + 1], ah[mt], fh[1], fh[3]);
                }
#pragma unroll
                for (int mt = 0; mt < 2; mt++) {
                    mma_bf16(acc[mt][n2 * 2],     ah[mt], fl[0], fl[2]);
                    mma_bf16(acc[mt][n2 * 2 + 1], ah[mt], fl[1], fl[3]);
                }
#pragma unroll
                for (int mt = 0; mt < 2; mt++) {
                    mma_bf16(acc[mt][n2 * 2],     al[mt], fh[0], fh[2]);
                    mma_bf16(acc[mt][n2 * 2 + 1], al[mt], fh[1], fh[3]);
                }
            }
        }

        if (s + 1 < NSLAB) CP_WAIT0();
        __syncthreads();
        buf ^= 1;
    }

    // ---- epilogue: bias + ELU; fp32 or bf16 hi/lo split output ----
#pragma unroll
    for (int mt = 0; mt < 2; mt++) {
#pragma unroll
        for (int nt = 0; nt < NT; nt++) {
            int col = o_off + wn * WN + nt * 8 + tid * 2;
            float b0 = bias[col], b1 = bias[col + 1];
            int r0 = n0 + wm * 32 + mt * 16 + gid;
            int r1 = r0 + 8;
            float v0 = elu(acc[mt][nt][0] + b0);
            float v1 = elu(acc[mt][nt][1] + b1);
            float v2 = elu(acc[mt][nt][2] + b0);
            float v3 = elu(acc[mt][nt][3] + b1);
            if constexpr (SPLIT) {
                if (r0 < N_NODES) {
                    float l0, l1;
                    uint32_t h = pack_hi2(v0, v1, l0, l1);
                    *reinterpret_cast<uint32_t*>(oh + (size_t)r0 * OTOT + col) = h;
                    *reinterpret_cast<uint32_t*>(ol + (size_t)r0 * OTOT + col) =
                        pack_lo2(l0, l1);
                }
                if (r1 < N_NODES) {
                    float l0, l1;
                    uint32_t h = pack_hi2(v2, v3, l0, l1);
                    *reinterpret_cast<uint32_t*>(oh + (size_t)r1 * OTOT + col) = h;
                    *reinterpret_cast<uint32_t*>(ol + (size_t)r1 * OTOT + col) =
                        pack_lo2(l0, l1);
                }
            } else {
                if (r0 < N_NODES) {
                    float2 v; v.x = v0; v.y = v1;
                    *reinterpret_cast<float2*>(outf + (size_t)r0 * OTOT + col) = v;
                }
                if (r1 < N_NODES) {
                    float2 v; v.x = v2; v.y = v3;
                    *reinterpret_cast<float2*>(outf + (size_t)r1 * OTOT + col) = v;
                }
            }
        }
    }
}

// ---------------------------------------------------------------------------
// fc2 + log_softmax: one warp per node. 12 outputs from 256 inputs.
// ---------------------------------------------------------------------------
__global__ __launch_bounds__(256) void fc2_lsm_kernel(
    const float* __restrict__ w,
    const float* __restrict__ bias,
    float* __restrict__ out)
{
    __shared__ float sw[12][256];
    __shared__ float sb[12];
    int t = threadIdx.x;
    for (int i = t; i < 12 * 256; i += 256) sw[i >> 8][i & 255] = w[i];
    if (t < 12) sb[t] = bias[t];
    __syncthreads();

    int node = blockIdx.x * 8 + (t >> 5);
    int lane = t & 31;
    if (node >= N_NODES) return;

    const float* row = g_h4 + (size_t)node * 256;
    float acc[12];
#pragma unroll
    for (int o = 0; o < 12; o++) acc[o] = 0.f;

#pragma unroll
    for (int r = 0; r < 8; r++) {
        float hv = row[lane + 32 * r];
#pragma unroll
        for (int o = 0; o < 12; o++) acc[o] += hv * sw[o][lane + 32 * r];
    }

#pragma unroll
    for (int o = 0; o < 12; o++) {
#pragma unroll
        for (int d = 16; d > 0; d >>= 1)
            acc[o] += __shfl_xor_sync(0xffffffffu, acc[o], d);
        acc[o] += sb[o];
    }

    float m = acc[0];
#pragma unroll
    for (int o = 1; o < 12; o++) m = fmaxf(m, acc[o]);
    float s = 0.f;
#pragma unroll
    for (int o = 0; o < 12; o++) s += expf(acc[o] - m);
    float lse = m + logf(s);

    if (lane < 12) out[(size_t)node * 12 + lane] = acc[lane] - lse;
}

// ---------------------------------------------------------------------------
// Launch
// ---------------------------------------------------------------------------
extern "C" void kernel_launch(void* const* d_in, const int* in_sizes, int n_in,
                              void* d_out, int out_size)
{
    const float* x      = (const float*)d_in[0];
    const int*   idxw   = (const int*)d_in[1];
    const float* fc0_w  = (const float*)d_in[2];
    const float* fc0_b  = (const float*)d_in[3];
    const float* w1     = (const float*)d_in[4];
    const float* b1     = (const float*)d_in[5];
    const float* w2     = (const float*)d_in[6];
    const float* b2     = (const float*)d_in[7];
    const float* w3     = (const float*)d_in[8];
    const float* b3     = (const float*)d_in[9];
    const float* fc1_w  = (const float*)d_in[10];
    const float* fc1_b  = (const float*)d_in[11];
    const float* fc2_w  = (const float*)d_in[12];
    const float* fc2_b  = (const float*)d_in[13];
    float* out = (float*)d_out;

    __nv_bfloat16 *h0h, *h0l, *h1h, *h1l, *h2h, *h2l, *h3h, *h3l;
    float* h4;
    cudaGetSymbolAddress((void**)&h0h, g_h0h);
    cudaGetSymbolAddress((void**)&h0l, g_h0l);
    cudaGetSymbolAddress((void**)&h1h, g_h1h);
    cudaGetSymbolAddress((void**)&h1l, g_h1l);
    cudaGetSymbolAddress((void**)&h2h, g_h2h);
    cudaGetSymbolAddress((void**)&h2l, g_h2l);
    cudaGetSymbolAddress((void**)&h3h, g_h3h);
    cudaGetSymbolAddress((void**)&h3l, g_h3l);
    cudaGetSymbolAddress((void**)&h4, g_h4);

    __nv_bfloat16 *w1h, *w1l, *w2h, *w2l, *w3h, *w3l, *f1h, *f1l;
    cudaGetSymbolAddress((void**)&w1h, g_w1h);
    cudaGetSymbolAddress((void**)&w1l, g_w1l);
    cudaGetSymbolAddress((void**)&w2h, g_w2h);
    cudaGetSymbolAddress((void**)&w2l, g_w2l);
    cudaGetSymbolAddress((void**)&w3h, g_w3h);
    cudaGetSymbolAddress((void**)&w3l, g_w3l);
    cudaGetSymbolAddress((void**)&f1h, g_f1h);
    cudaGetSymbolAddress((void**)&f1l, g_f1l);

    // dynamic smem: 2 * (2*32K A + 2*OT*128 B) + 16K idx
    const int SM_L1  = 2 * (65536 + 2 * 32 * 128) + 16384;    // 163840
    const int SM_L2  = 2 * (65536 + 2 * 64 * 128) + 16384;    // 180224
    const int SM_L3  = 2 * (65536 + 2 * 128 * 128) + 16384;   // 212992
    const int SM_FC1 = SM_L3;

    static int attr_set = 0;
    if (!attr_set) {
        cudaFuncSetAttribute(mma_gemm_kernel<256, 32, 32, 16, true>,
                             cudaFuncAttributeMaxDynamicSharedMemorySize, SM_L1);
        cudaFuncSetAttribute(mma_gemm_kernel<512, 64, 64, 32, true>,
                             cudaFuncAttributeMaxDynamicSharedMemorySize, SM_L2);
        cudaFuncSetAttribute(mma_gemm_kernel<1024, 128, 128, 64, true>,
                             cudaFuncAttributeMaxDynamicSharedMemorySize, SM_L3);
        cudaFuncSetAttribute(mma_gemm_kernel<128, 256, 128, 0, false>,
                             cudaFuncAttributeMaxDynamicSharedMemorySize, SM_FC1);
        attr_set = 1;
    }

    const int NB = (N_NODES + 255) / 256;   // BM = 256

    detect_idx_kernel<<<1, 32>>>(idxw);                               // 0
    conv_idx_kernel<<<(N_NODES * SEQ + 255) / 256, 256>>>(idxw);      // 1
    split_all_kernel<<<(204800 + 255) / 256, 256>>>(w1, w2, w3, fc1_w); // 2
    fc0_kernel<<<(N_NODES + 255) / 256, 256>>>(x, fc0_w, fc0_b);      // 3

    // spiral conv 1: C=16, K=256, O=32                               // 4
    mma_gemm_kernel<256, 32, 32, 16, true><<<dim3(NB, 1), 512, SM_L1>>>(
        h0h, h0l, w1h, w1l, b1, nullptr, h1h, h1l);
    // spiral conv 2: C=32, K=512, O=64                               // 5 (ncu)
    mma_gemm_kernel<512, 64, 64, 32, true><<<dim3(NB, 1), 512, SM_L2>>>(
        h1h, h1l, w2h, w2l, b2, nullptr, h2h, h2l);
    // spiral conv 3: C=64, K=1024, O=128                             // 6
    mma_gemm_kernel<1024, 128, 128, 64, true><<<dim3(NB, 1), 512, SM_L3>>>(
        h2h, h2l, w3h, w3l, b3, nullptr, h3h, h3l);
    // fc1 dense: K=128, O=256 (2 output tiles)                       // 7
    mma_gemm_kernel<128, 256, 128, 0, false><<<dim3(NB, 2), 512, SM_FC1>>>(
        h3h, h3l, f1h, f1l, fc1_b, h4, nullptr, nullptr);
    // fc2 + log_softmax                                              // 8
    fc2_lsm_kernel<<<(N_NODES + 7) / 8, 256>>>(fc2_w, fc2_b, out);
}

// round 9
// speedup vs baseline: 3.6335x; 1.3899x over previous
#include <cuda_runtime.h>
#include <cuda_fp16.h>
#include <math.h>
#include <stdint.h>

#define N_NODES 100000
#define SEQ 16

// Scratch activations as single fp16 (device globals: no allocation).
__device__ __align__(16) __half g_h0[N_NODES * 16];
__device__ __align__(16) __half g_h1[N_NODES * 32];
__device__ __align__(16) __half g_h2[N_NODES * 64];
__device__ __align__(16) __half g_h3[N_NODES * 128];
__device__ __align__(16) float  g_h4[N_NODES * 256];
__device__ int g_idx[N_NODES * SEQ];
__device__ int g_is64;
// weights split into fp16 hi/lo (prepared once per launch)
__device__ __align__(16) __half g_w1h[32 * 256];
__device__ __align__(16) __half g_w1l[32 * 256];
__device__ __align__(16) __half g_w2h[64 * 512];
__device__ __align__(16) __half g_w2l[64 * 512];
__device__ __align__(16) __half g_w3h[128 * 1024];
__device__ __align__(16) __half g_w3l[128 * 1024];
__device__ __align__(16) __half g_f1h[256 * 128];
__device__ __align__(16) __half g_f1l[256 * 128];

__device__ __forceinline__ float elu(float v) {
    return v > 0.f ? v : expm1f(v);
}

// ---------------- helpers ----------------
__device__ __forceinline__ uint32_t smem_to_u32(const void* p) {
    uint32_t a;
    asm("{ .reg .u64 tmp; cvta.to.shared.u64 tmp, %1; cvt.u32.u64 %0, tmp; }"
        : "=r"(a) : "l"(p));
    return a;
}
#define SWZ(b) ((b) ^ (((b) >> 3) & 0x70))

__device__ __forceinline__ void ldsm_x4(uint32_t* r, uint32_t addr) {
    asm volatile(
        "ldmatrix.sync.aligned.m8n8.x4.shared.b16 {%0,%1,%2,%3}, [%4];"
        : "=r"(r[0]), "=r"(r[1]), "=r"(r[2]), "=r"(r[3]) : "r"(addr));
}
__device__ __forceinline__ void mma_f16(float* c, const uint32_t* a,
                                        uint32_t b0, uint32_t b1) {
    asm volatile(
        "mma.sync.aligned.m16n8k16.row.col.f32.f16.f16.f32 "
        "{%0,%1,%2,%3}, {%4,%5,%6,%7}, {%8,%9}, {%0,%1,%2,%3};"
        : "+f"(c[0]), "+f"(c[1]), "+f"(c[2]), "+f"(c[3])
        : "r"(a[0]), "r"(a[1]), "r"(a[2]), "r"(a[3]), "r"(b0), "r"(b1));
}
__device__ __forceinline__ void cp16(uint32_t dst, const void* src) {
    asm volatile("cp.async.ca.shared.global [%0], [%1], 16;"
                 :: "r"(dst), "l"(src));
}
#define CP_COMMIT() asm volatile("cp.async.commit_group;" ::: "memory")
#define CP_WAIT0()  asm volatile("cp.async.wait_group 0;" ::: "memory")

__device__ __forceinline__ uint32_t packh2(float a, float b) {
    __half2 h = __floats2half2_rn(a, b);
    return *reinterpret_cast<uint32_t*>(&h);
}

// ---------------------------------------------------------------------------
// Index dtype detection + conversion (reference declares int64; JAX default
// x64-off actually yields int32 — detect on device, clamp for safety).
// ---------------------------------------------------------------------------
__global__ void detect_idx_kernel(const int* __restrict__ w32) {
    if (threadIdx.x == 0) {
        int all_zero = 1;
        for (int k = 0; k < 64; k++) {
            if (w32[2 * k * 1024 + 1] != 0) { all_zero = 0; break; }
        }
        g_is64 = all_zero;
    }
}
__global__ void conv_idx_kernel(const int* __restrict__ w32) {
    int i = blockIdx.x * blockDim.x + threadIdx.x;
    if (i >= N_NODES * SEQ) return;
    int v = g_is64 ? w32[2 * i] : w32[i];
    if (v < 0) v = 0;
    if (v >= N_NODES) v = N_NODES - 1;
    g_idx[i] = v;
}

// ---------------------------------------------------------------------------
// All four weight splits in one kernel: fp16 hi + fp16 residual.
// ---------------------------------------------------------------------------
__global__ void split_all_kernel(const float* __restrict__ w1,
                                 const float* __restrict__ w2,
                                 const float* __restrict__ w3,
                                 const float* __restrict__ f1) {
    int i = blockIdx.x * blockDim.x + threadIdx.x;
    const float* src;
    __half *hi, *lo;
    int off;
    if (i < 8192)              { src = w1; hi = g_w1h; lo = g_w1l; off = i; }
    else if (i < 8192 + 32768) { src = w2; hi = g_w2h; lo = g_w2l; off = i - 8192; }
    else if (i < 8192 + 32768 + 131072) {
        src = w3; hi = g_w3h; lo = g_w3l; off = i - 8192 - 32768;
    } else if (i < 8192 + 32768 + 131072 + 32768) {
        src = f1; hi = g_f1h; lo = g_f1l; off = i - 8192 - 32768 - 131072;
    } else return;
    float v = src[off];
    __half h = __float2half_rn(v);
    hi[off] = h;
    lo[off] = __float2half_rn(v - __half2float(h));
}

// ---------------------------------------------------------------------------
// fc0: [N,3] @ [3,16]^T + b, ELU -> fp16 output.
// ---------------------------------------------------------------------------
__global__ __launch_bounds__(256) void fc0_kernel(
    const float* __restrict__ x,
    const float* __restrict__ w,
    const float* __restrict__ bias)
{
    __shared__ float sw[48];
    __shared__ float sb[16];
    if (threadIdx.x < 48) sw[threadIdx.x] = w[threadIdx.x];
    if (threadIdx.x < 16) sb[threadIdx.x] = bias[threadIdx.x];
    __syncthreads();

    int n = blockIdx.x * blockDim.x + threadIdx.x;
    if (n >= N_NODES) return;

    float x0 = x[n * 3 + 0], x1 = x[n * 3 + 1], x2 = x[n * 3 + 2];
    uint32_t h[8];
#pragma unroll
    for (int j = 0; j < 8; j++) {
        float v0 = sb[2 * j] + sw[(2 * j) * 3] * x0 + sw[(2 * j) * 3 + 1] * x1 +
                   sw[(2 * j) * 3 + 2] * x2;
        float v1 = sb[2 * j + 1] + sw[(2 * j + 1) * 3] * x0 +
                   sw[(2 * j + 1) * 3 + 1] * x1 + sw[(2 * j + 1) * 3 + 2] * x2;
        h[j] = packh2(elu(v0), elu(v1));
    }
    uint4* dh = reinterpret_cast<uint4*>(g_h0 + (size_t)n * 16);
    dh[0] = make_uint4(h[0], h[1], h[2], h[3]);
    dh[1] = make_uint4(h[4], h[5], h[6], h[7]);
}

// ---------------------------------------------------------------------------
// Warp-MMA gathered GEMM: fp16 activations (single), fp16 hi/lo weights,
// fp32 accum, 2 terms: A*Wh + A*Wl  (err ~2^-12, budget 1e-3).
// BM=256 nodes x OT outputs per block, 512 threads (16 warps as 8x2,
// warp tile 32 x WN). BK=64 fp16 k-slab; cp.async 16B gather-copy into
// swizzled smem, double-buffered, one __syncthreads per slab.
// C: input channels per neighbor (0 = dense).
// ---------------------------------------------------------------------------
template <int K, int OTOT, int OT, int C, bool SPLIT>
__global__ __launch_bounds__(512, 1) void mma_gemm_kernel(
    const __half* __restrict__ pa,
    const __half* __restrict__ wh,
    const __half* __restrict__ wl,
    const float* __restrict__ bias,
    float* __restrict__ outf,
    __half* __restrict__ oh)
{
    constexpr int BM     = 256;
    constexpr int NSLAB  = K / 64;
    constexpr int WN     = OT / 2;
    constexpr int NT     = WN / 8;
    constexpr int NT2    = WN / 16;
    constexpr int ACH    = BM * 8 / 512;      // A 16B chunks / thread
    constexpr int BCH    = OT * 16 / 512;     // B 16B chunks / thread (2 parts)
    constexpr uint32_t ABYTES = BM * 128;     // 32 KB (single part)
    constexpr uint32_t BBYTES = OT * 128;     // per part
    constexpr uint32_t BUF    = ABYTES + 2 * BBYTES;

    extern __shared__ char smem[];
    const uint32_t sbu = smem_to_u32(smem);
    int* sIdx = reinterpret_cast<int*>(smem + 2 * BUF);

    const int t    = threadIdx.x;
    const int wid  = t >> 5;
    const int lane = t & 31;
    const int wm   = wid & 7;        // 8 warps along M
    const int wn   = wid >> 3;       // 2 warps along N
    const int gid  = lane >> 2;
    const int tid  = lane & 3;
    const int n0   = blockIdx.x * BM;
    const int o_off = blockIdx.y * OT;

    if constexpr (C > 0) {
        for (int i = t; i < BM * SEQ; i += 512) {
            int node = n0 + (i >> 4);
            if (node > N_NODES - 1) node = N_NODES - 1;
            sIdx[i] = g_idx[node * SEQ + (i & 15)];
        }
        __syncthreads();
    }

    auto issue_copy = [&](int s, int buf) {
        uint32_t base = sbu + buf * BUF;
#pragma unroll
        for (int j = 0; j < ACH; j++) {
            int id  = t + 512 * j;
            int row = id >> 3;
            int c   = id & 7;
            int kg  = s * 64 + c * 8;
            const __half* src;
            if constexpr (C == 0) {
                int node = n0 + row;
                if (node > N_NODES - 1) node = N_NODES - 1;
                src = pa + (size_t)node * K + kg;
            } else {
                int sn = sIdx[row * SEQ + kg / C];
                src = pa + (size_t)sn * C + (kg % C);
            }
            uint32_t dst = base + SWZ((uint32_t)(row * 128 + c * 16));
            cp16(dst, src);
        }
#pragma unroll
        for (int j = 0; j < BCH; j++) {
            int id   = t + 512 * j;
            int o    = id >> 4;
            int cc   = id & 15;
            int part = cc >> 3;
            int c    = cc & 7;
            const __half* src =
                (part ? wl : wh) + (size_t)(o_off + o) * K + s * 64 + c * 8;
            uint32_t dst = base + ABYTES + part * BBYTES +
                           SWZ((uint32_t)(o * 128 + c * 16));
            cp16(dst, src);
        }
        CP_COMMIT();
    };

    float acc[2][NT][4];
#pragma unroll
    for (int m = 0; m < 2; m++)
#pragma unroll
        for (int n = 0; n < NT; n++)
#pragma unroll
            for (int q = 0; q < 4; q++) acc[m][n][q] = 0.f;

    issue_copy(0, 0);
    CP_WAIT0();
    __syncthreads();

    const uint32_t flrow  = lane & 15;
    const uint32_t fchalf = (lane >> 4) * 16;

    int buf = 0;
    for (int s = 0; s < NSLAB; s++) {
        if (s + 1 < NSLAB) issue_copy(s + 1, buf ^ 1);

        uint32_t base = sbu + buf * BUF;
#pragma unroll
        for (int kc = 0; kc < 4; kc++) {
            uint32_t colb = kc * 32 + fchalf;
            uint32_t ah[2][4];
#pragma unroll
            for (int mt = 0; mt < 2; mt++) {
                uint32_t off = (wm * 32 + mt * 16 + flrow) * 128 + colb;
                ldsm_x4(ah[mt], base + SWZ(off));
            }
#pragma unroll
            for (int n2 = 0; n2 < NT2; n2++) {
                uint32_t off = (wn * WN + n2 * 16 + flrow) * 128 + colb;
                uint32_t sw  = SWZ(off);
                uint32_t fh[4], fl[4];
                ldsm_x4(fh, base + ABYTES + sw);
                ldsm_x4(fl, base + ABYTES + BBYTES + sw);
#pragma unroll
                for (int mt = 0; mt < 2; mt++) {
                    mma_f16(acc[mt][n2 * 2],     ah[mt], fh[0], fh[2]);
                    mma_f16(acc[mt][n2 * 2 + 1], ah[mt], fh[1], fh[3]);
                }
#pragma unroll
                for (int mt = 0; mt < 2; mt++) {
                    mma_f16(acc[mt][n2 * 2],     ah[mt], fl[0], fl[2]);
                    mma_f16(acc[mt][n2 * 2 + 1], ah[mt], fl[1], fl[3]);
                }
            }
        }

        if (s + 1 < NSLAB) CP_WAIT0();
        __syncthreads();
        buf ^= 1;
    }

    // ---- epilogue: bias + ELU; fp32 or fp16 output ----
#pragma unroll
    for (int mt = 0; mt < 2; mt++) {
#pragma unroll
        for (int nt = 0; nt < NT; nt++) {
            int col = o_off + wn * WN + nt * 8 + tid * 2;
            float b0 = bias[col], b1 = bias[col + 1];
            int r0 = n0 + wm * 32 + mt * 16 + gid;
            int r1 = r0 + 8;
            float v0 = elu(acc[mt][nt][0] + b0);
            float v1 = elu(acc[mt][nt][1] + b1);
            float v2 = elu(acc[mt][nt][2] + b0);
            float v3 = elu(acc[mt][nt][3] + b1);
            if constexpr (SPLIT) {
                if (r0 < N_NODES)
                    *reinterpret_cast<uint32_t*>(oh + (size_t)r0 * OTOT + col) =
                        packh2(v0, v1);
                if (r1 < N_NODES)
                    *reinterpret_cast<uint32_t*>(oh + (size_t)r1 * OTOT + col) =
                        packh2(v2, v3);
            } else {
                if (r0 < N_NODES) {
                    float2 v; v.x = v0; v.y = v1;
                    *reinterpret_cast<float2*>(outf + (size_t)r0 * OTOT + col) = v;
                }
                if (r1 < N_NODES) {
                    float2 v; v.x = v2; v.y = v3;
                    *reinterpret_cast<float2*>(outf + (size_t)r1 * OTOT + col) = v;
                }
            }
        }
    }
}

// ---------------------------------------------------------------------------
// fc2 + log_softmax: one warp per node. 12 outputs from 256 inputs.
// ---------------------------------------------------------------------------
__global__ __launch_bounds__(256) void fc2_lsm_kernel(
    const float* __restrict__ w,
    const float* __restrict__ bias,
    float* __restrict__ out)
{
    __shared__ float sw[12][256];
    __shared__ float sb[12];
    int t = threadIdx.x;
    for (int i = t; i < 12 * 256; i += 256) sw[i >> 8][i & 255] = w[i];
    if (t < 12) sb[t] = bias[t];
    __syncthreads();

    int node = blockIdx.x * 8 + (t >> 5);
    int lane = t & 31;
    if (node >= N_NODES) return;

    const float* row = g_h4 + (size_t)node * 256;
    float acc[12];
#pragma unroll
    for (int o = 0; o < 12; o++) acc[o] = 0.f;

#pragma unroll
    for (int r = 0; r < 8; r++) {
        float hv = row[lane + 32 * r];
#pragma unroll
        for (int o = 0; o < 12; o++) acc[o] += hv * sw[o][lane + 32 * r];
    }

#pragma unroll
    for (int o = 0; o < 12; o++) {
#pragma unroll
        for (int d = 16; d > 0; d >>= 1)
            acc[o] += __shfl_xor_sync(0xffffffffu, acc[o], d);
        acc[o] += sb[o];
    }

    float m = acc[0];
#pragma unroll
    for (int o = 1; o < 12; o++) m = fmaxf(m, acc[o]);
    float s = 0.f;
#pragma unroll
    for (int o = 0; o < 12; o++) s += expf(acc[o] - m);
    float lse = m + logf(s);

    if (lane < 12) out[(size_t)node * 12 + lane] = acc[lane] - lse;
}

// ---------------------------------------------------------------------------
// Launch
// ---------------------------------------------------------------------------
extern "C" void kernel_launch(void* const* d_in, const int* in_sizes, int n_in,
                              void* d_out, int out_size)
{
    const float* x      = (const float*)d_in[0];
    const int*   idxw   = (const int*)d_in[1];
    const float* fc0_w  = (const float*)d_in[2];
    const float* fc0_b  = (const float*)d_in[3];
    const float* w1     = (const float*)d_in[4];
    const float* b1     = (const float*)d_in[5];
    const float* w2     = (const float*)d_in[6];
    const float* b2     = (const float*)d_in[7];
    const float* w3     = (const float*)d_in[8];
    const float* b3     = (const float*)d_in[9];
    const float* fc1_w  = (const float*)d_in[10];
    const float* fc1_b  = (const float*)d_in[11];
    const float* fc2_w  = (const float*)d_in[12];
    const float* fc2_b  = (const float*)d_in[13];
    float* out = (float*)d_out;

    __half *h0, *h1, *h2, *h3;
    float* h4;
    cudaGetSymbolAddress((void**)&h0, g_h0);
    cudaGetSymbolAddress((void**)&h1, g_h1);
    cudaGetSymbolAddress((void**)&h2, g_h2);
    cudaGetSymbolAddress((void**)&h3, g_h3);
    cudaGetSymbolAddress((void**)&h4, g_h4);

    __half *w1h, *w1l, *w2h, *w2l, *w3h, *w3l, *f1h, *f1l;
    cudaGetSymbolAddress((void**)&w1h, g_w1h);
    cudaGetSymbolAddress((void**)&w1l, g_w1l);
    cudaGetSymbolAddress((void**)&w2h, g_w2h);
    cudaGetSymbolAddress((void**)&w2l, g_w2l);
    cudaGetSymbolAddress((void**)&w3h, g_w3h);
    cudaGetSymbolAddress((void**)&w3l, g_w3l);
    cudaGetSymbolAddress((void**)&f1h, g_f1h);
    cudaGetSymbolAddress((void**)&f1l, g_f1l);

    // dynamic smem: 2 * (32K A + 2*OT*128 B) + 16K idx
    const int SM_L1  = 2 * (32768 + 2 * 32 * 128) + 16384;    //  98304
    const int SM_L2  = 2 * (32768 + 2 * 64 * 128) + 16384;    // 114688
    const int SM_L3  = 2 * (32768 + 2 * 128 * 128) + 16384;   // 147456
    const int SM_FC1 = SM_L3;

    static int attr_set = 0;
    if (!attr_set) {
        cudaFuncSetAttribute(mma_gemm_kernel<256, 32, 32, 16, true>,
                             cudaFuncAttributeMaxDynamicSharedMemorySize, SM_L1);
        cudaFuncSetAttribute(mma_gemm_kernel<512, 64, 64, 32, true>,
                             cudaFuncAttributeMaxDynamicSharedMemorySize, SM_L2);
        cudaFuncSetAttribute(mma_gemm_kernel<1024, 128, 128, 64, true>,
                             cudaFuncAttributeMaxDynamicSharedMemorySize, SM_L3);
        cudaFuncSetAttribute(mma_gemm_kernel<128, 256, 128, 0, false>,
                             cudaFuncAttributeMaxDynamicSharedMemorySize, SM_FC1);
        attr_set = 1;
    }

    const int NB = (N_NODES + 255) / 256;   // BM = 256

    detect_idx_kernel<<<1, 32>>>(idxw);
    conv_idx_kernel<<<(N_NODES * SEQ + 255) / 256, 256>>>(idxw);
    split_all_kernel<<<(204800 + 255) / 256, 256>>>(w1, w2, w3, fc1_w);
    fc0_kernel<<<(N_NODES + 255) / 256, 256>>>(x, fc0_w, fc0_b);

    // spiral conv 1: C=16, K=256, O=32
    mma_gemm_kernel<256, 32, 32, 16, true><<<dim3(NB, 1), 512, SM_L1>>>(
        h0, w1h, w1l, b1, nullptr, h1);
    // spiral conv 2: C=32, K=512, O=64
    mma_gemm_kernel<512, 64, 64, 32, true><<<dim3(NB, 1), 512, SM_L2>>>(
        h1, w2h, w2l, b2, nullptr, h2);
    // spiral conv 3: C=64, K=1024, O=128
    mma_gemm_kernel<1024, 128, 128, 64, true><<<dim3(NB, 1), 512, SM_L3>>>(
        h2, w3h, w3l, b3, nullptr, h3);
    // fc1 dense: K=128, O=256 (2 output tiles)
    mma_gemm_kernel<128, 256, 128, 0, false><<<dim3(NB, 2), 512, SM_FC1>>>(
        h3, f1h, f1l, fc1_b, h4, nullptr);
    // fc2 + log_softmax
    fc2_lsm_kernel<<<(N_NODES + 7) / 8, 256>>>(fc2_w, fc2_b, out);
}

// round 11
// speedup vs baseline: 4.5986x; 1.2656x over previous
#include <cuda_runtime.h>
#include <cuda_fp16.h>
#include <math.h>
#include <stdint.h>

#define N_NODES 100000
#define SEQ 16

// Scratch activations as fp16 (device globals: no allocation).
__device__ __align__(16) __half g_h0[N_NODES * 16];
__device__ __align__(16) __half g_h1[N_NODES * 32];
__device__ __align__(16) __half g_h2[N_NODES * 64];
__device__ __align__(16) __half g_h3[N_NODES * 128];
__device__ __align__(16) float  g_h4[N_NODES * 256];
__device__ int g_idx[N_NODES * SEQ];
__device__ int g_is64;
// weights as fp16 (prepared once per launch)
__device__ __align__(16) __half g_w1[32 * 256];
__device__ __align__(16) __half g_w2[64 * 512];
__device__ __align__(16) __half g_w3[128 * 1024];
__device__ __align__(16) __half g_f1[256 * 128];

__device__ __forceinline__ float elu(float v) {
    return v > 0.f ? v : expm1f(v);
}

// ---------------- helpers ----------------
__device__ __forceinline__ uint32_t smem_to_u32(const void* p) {
    uint32_t a;
    asm("{ .reg .u64 tmp; cvta.to.shared.u64 tmp, %1; cvt.u32.u64 %0, tmp; }"
        : "=r"(a) : "l"(p));
    return a;
}
#define SWZ(b) ((b) ^ (((b) >> 3) & 0x70))

__device__ __forceinline__ void ldsm_x4(uint32_t* r, uint32_t addr) {
    asm volatile(
        "ldmatrix.sync.aligned.m8n8.x4.shared.b16 {%0,%1,%2,%3}, [%4];"
        : "=r"(r[0]), "=r"(r[1]), "=r"(r[2]), "=r"(r[3]) : "r"(addr));
}
__device__ __forceinline__ void mma_f16(float* c, const uint32_t* a,
                                        uint32_t b0, uint32_t b1) {
    asm volatile(
        "mma.sync.aligned.m16n8k16.row.col.f32.f16.f16.f32 "
        "{%0,%1,%2,%3}, {%4,%5,%6,%7}, {%8,%9}, {%0,%1,%2,%3};"
        : "+f"(c[0]), "+f"(c[1]), "+f"(c[2]), "+f"(c[3])
        : "r"(a[0]), "r"(a[1]), "r"(a[2]), "r"(a[3]), "r"(b0), "r"(b1));
}
__device__ __forceinline__ void cp16(uint32_t dst, const void* src) {
    asm volatile("cp.async.ca.shared.global [%0], [%1], 16;"
                 :: "r"(dst), "l"(src));
}
#define CP_COMMIT() asm volatile("cp.async.commit_group;" ::: "memory")
#define CP_WAIT0()  asm volatile("cp.async.wait_group 0;" ::: "memory")

__device__ __forceinline__ uint32_t packh2(float a, float b) {
    __half2 h = __floats2half2_rn(a, b);
    return *reinterpret_cast<uint32_t*>(&h);
}

// ---------------------------------------------------------------------------
// Index dtype detection + conversion (reference declares int64; JAX default
// x64-off actually yields int32 — detect on device, clamp for safety).
// ---------------------------------------------------------------------------
__global__ void detect_idx_kernel(const int* __restrict__ w32) {
    if (threadIdx.x == 0) {
        int all_zero = 1;
        for (int k = 0; k < 64; k++) {
            if (w32[2 * k * 1024 + 1] != 0) { all_zero = 0; break; }
        }
        g_is64 = all_zero;
    }
}
__global__ void conv_idx_kernel(const int* __restrict__ w32) {
    int i = blockIdx.x * blockDim.x + threadIdx.x;
    if (i >= N_NODES * SEQ) return;
    int v = g_is64 ? w32[2 * i] : w32[i];
    if (v < 0) v = 0;
    if (v >= N_NODES) v = N_NODES - 1;
    g_idx[i] = v;
}

// ---------------------------------------------------------------------------
// All four weight conversions (fp32 -> fp16) in one kernel.
// ---------------------------------------------------------------------------
__global__ void conv_w_kernel(const float* __restrict__ w1,
                              const float* __restrict__ w2,
                              const float* __restrict__ w3,
                              const float* __restrict__ f1) {
    int i = blockIdx.x * blockDim.x + threadIdx.x;
    const float* src;
    __half* dst;
    int off;
    if (i < 8192)              { src = w1; dst = g_w1; off = i; }
    else if (i < 8192 + 32768) { src = w2; dst = g_w2; off = i - 8192; }
    else if (i < 8192 + 32768 + 131072) {
        src = w3; dst = g_w3; off = i - 8192 - 32768;
    } else if (i < 8192 + 32768 + 131072 + 32768) {
        src = f1; dst = g_f1; off = i - 8192 - 32768 - 131072;
    } else return;
    dst[off] = __float2half_rn(src[off]);
}

// ---------------------------------------------------------------------------
// fc0: [N,3] @ [3,16]^T + b, ELU -> fp16 output.
// ---------------------------------------------------------------------------
__global__ __launch_bounds__(256) void fc0_kernel(
    const float* __restrict__ x,
    const float* __restrict__ w,
    const float* __restrict__ bias)
{
    __shared__ float sw[48];
    __shared__ float sb[16];
    if (threadIdx.x < 48) sw[threadIdx.x] = w[threadIdx.x];
    if (threadIdx.x < 16) sb[threadIdx.x] = bias[threadIdx.x];
    __syncthreads();

    int n = blockIdx.x * blockDim.x + threadIdx.x;
    if (n >= N_NODES) return;

    float x0 = x[n * 3 + 0], x1 = x[n * 3 + 1], x2 = x[n * 3 + 2];
    uint32_t h[8];
#pragma unroll
    for (int j = 0; j < 8; j++) {
        float v0 = sb[2 * j] + sw[(2 * j) * 3] * x0 + sw[(2 * j) * 3 + 1] * x1 +
                   sw[(2 * j) * 3 + 2] * x2;
        float v1 = sb[2 * j + 1] + sw[(2 * j + 1) * 3] * x0 +
                   sw[(2 * j + 1) * 3 + 1] * x1 + sw[(2 * j + 1) * 3 + 2] * x2;
        h[j] = packh2(elu(v0), elu(v1));
    }
    uint4* dh = reinterpret_cast<uint4*>(g_h0 + (size_t)n * 16);
    dh[0] = make_uint4(h[0], h[1], h[2], h[3]);
    dh[1] = make_uint4(h[4], h[5], h[6], h[7]);
}

// ---------------------------------------------------------------------------
// Warp-MMA gathered GEMM: fp16 x fp16, fp32 accum, single term.
// BM=256 nodes x OT outputs per block, 512 threads (16 warps as 8x2,
// warp tile 32 x WN). BK=64 fp16 k-slab; cp.async 16B gather-copy into
// swizzled smem, double-buffered, one __syncthreads per slab.
// C: input channels per neighbor (0 = dense).
// ---------------------------------------------------------------------------
template <int K, int OTOT, int OT, int C, bool SPLIT>
__global__ __launch_bounds__(512, 1) void mma_gemm_kernel(
    const __half* __restrict__ pa,
    const __half* __restrict__ wg,
    const float* __restrict__ bias,
    float* __restrict__ outf,
    __half* __restrict__ oh)
{
    constexpr int BM     = 256;
    constexpr int NSLAB  = K / 64;
    constexpr int WN     = OT / 2;
    constexpr int NT     = WN / 8;
    constexpr int NT2    = WN / 16;
    constexpr int ACH    = BM * 8 / 512;            // A 16B chunks / thread
    constexpr int BTOT   = OT * 8;                  // B 16B chunks total
    constexpr int BCH    = (BTOT + 511) / 512;      // ceil-div (BUGFIX: was 0 for OT=32)
    constexpr uint32_t ABYTES = BM * 128;           // 32 KB
    constexpr uint32_t BBYTES = OT * 128;
    constexpr uint32_t BUF    = ABYTES + BBYTES;

    extern __shared__ char smem[];
    const uint32_t sbu = smem_to_u32(smem);
    int* sIdx = reinterpret_cast<int*>(smem + 2 * BUF);

    const int t    = threadIdx.x;
    const int wid  = t >> 5;
    const int lane = t & 31;
    const int wm   = wid & 7;        // 8 warps along M
    const int wn   = wid >> 3;       // 2 warps along N
    const int gid  = lane >> 2;
    const int tid  = lane & 3;
    const int n0   = blockIdx.x * BM;
    const int o_off = blockIdx.y * OT;

    if constexpr (C > 0) {
        for (int i = t; i < BM * SEQ; i += 512) {
            int node = n0 + (i >> 4);
            if (node > N_NODES - 1) node = N_NODES - 1;
            sIdx[i] = g_idx[node * SEQ + (i & 15)];
        }
        __syncthreads();
    }

    auto issue_copy = [&](int s, int buf) {
        uint32_t base = sbu + buf * BUF;
#pragma unroll
        for (int j = 0; j < ACH; j++) {
            int id  = t + 512 * j;
            int row = id >> 3;
            int c   = id & 7;
            int kg  = s * 64 + c * 8;
            const __half* src;
            if constexpr (C == 0) {
                int node = n0 + row;
                if (node > N_NODES - 1) node = N_NODES - 1;
                src = pa + (size_t)node * K + kg;
            } else {
                int sn = sIdx[row * SEQ + kg / C];
                src = pa + (size_t)sn * C + (kg % C);
            }
            uint32_t dst = base + SWZ((uint32_t)(row * 128 + c * 16));
            cp16(dst, src);
        }
#pragma unroll
        for (int j = 0; j < BCH; j++) {
            int id = t + 512 * j;
            if (id < BTOT) {                         // guard (BUGFIX)
                int o = id >> 3;
                int c = id & 7;
                const __half* src =
                    wg + (size_t)(o_off + o) * K + s * 64 + c * 8;
                uint32_t dst = base + ABYTES +
                               SWZ((uint32_t)(o * 128 + c * 16));
                cp16(dst, src);
            }
        }
        CP_COMMIT();
    };

    float acc[2][NT][4];
#pragma unroll
    for (int m = 0; m < 2; m++)
#pragma unroll
        for (int n = 0; n < NT; n++)
#pragma unroll
            for (int q = 0; q < 4; q++) acc[m][n][q] = 0.f;

    issue_copy(0, 0);
    CP_WAIT0();
    __syncthreads();

    const uint32_t flrow  = lane & 15;
    const uint32_t fchalf = (lane >> 4) * 16;

    int buf = 0;
    for (int s = 0; s < NSLAB; s++) {
        if (s + 1 < NSLAB) issue_copy(s + 1, buf ^ 1);

        uint32_t base = sbu + buf * BUF;
#pragma unroll
        for (int kc = 0; kc < 4; kc++) {
            uint32_t colb = kc * 32 + fchalf;
            uint32_t ah[2][4];
#pragma unroll
            for (int mt = 0; mt < 2; mt++) {
                uint32_t off = (wm * 32 + mt * 16 + flrow) * 128 + colb;
                ldsm_x4(ah[mt], base + SWZ(off));
            }
#pragma unroll
            for (int n2 = 0; n2 < NT2; n2++) {
                uint32_t off = (wn * WN + n2 * 16 + flrow) * 128 + colb;
                uint32_t sw  = SWZ(off);
                uint32_t fh[4];
                ldsm_x4(fh, base + ABYTES + sw);
#pragma unroll
                for (int mt = 0; mt < 2; mt++) {
                    mma_f16(acc[mt][n2 * 2],     ah[mt], fh[0], fh[2]);
                    mma_f16(acc[mt][n2 * 2 + 1], ah[mt], fh[1], fh[3]);
                }
            }
        }

        if (s + 1 < NSLAB) CP_WAIT0();
        __syncthreads();
        buf ^= 1;
    }

    // ---- epilogue: bias + ELU; fp32 or fp16 output ----
#pragma unroll
    for (int mt = 0; mt < 2; mt++) {
#pragma unroll
        for (int nt = 0; nt < NT; nt++) {
            int col = o_off + wn * WN + nt * 8 + tid * 2;
            float b0 = bias[col], b1 = bias[col + 1];
            int r0 = n0 + wm * 32 + mt * 16 + gid;
            int r1 = r0 + 8;
            float v0 = elu(acc[mt][nt][0] + b0);
            float v1 = elu(acc[mt][nt][1] + b1);
            float v2 = elu(acc[mt][nt][2] + b0);
            float v3 = elu(acc[mt][nt][3] + b1);
            if constexpr (SPLIT) {
                if (r0 < N_NODES)
                    *reinterpret_cast<uint32_t*>(oh + (size_t)r0 * OTOT + col) =
                        packh2(v0, v1);
                if (r1 < N_NODES)
                    *reinterpret_cast<uint32_t*>(oh + (size_t)r1 * OTOT + col) =
                        packh2(v2, v3);
            } else {
                if (r0 < N_NODES) {
                    float2 v; v.x = v0; v.y = v1;
                    *reinterpret_cast<float2*>(outf + (size_t)r0 * OTOT + col) = v;
                }
                if (r1 < N_NODES) {
                    float2 v; v.x = v2; v.y = v3;
                    *reinterpret_cast<float2*>(outf + (size_t)r1 * OTOT + col) = v;
                }
            }
        }
    }
}

// ---------------------------------------------------------------------------
// fc2 + log_softmax: one warp per node. 12 outputs from 256 inputs.
// ---------------------------------------------------------------------------
__global__ __launch_bounds__(256) void fc2_lsm_kernel(
    const float* __restrict__ w,
    const float* __restrict__ bias,
    float* __restrict__ out)
{
    __shared__ float sw[12][256];
    __shared__ float sb[12];
    int t = threadIdx.x;
    for (int i = t; i < 12 * 256; i += 256) sw[i >> 8][i & 255] = w[i];
    if (t < 12) sb[t] = bias[t];
    __syncthreads();

    int node = blockIdx.x * 8 + (t >> 5);
    int lane = t & 31;
    if (node >= N_NODES) return;

    const float* row = g_h4 + (size_t)node * 256;
    float acc[12];
#pragma unroll
    for (int o = 0; o < 12; o++) acc[o] = 0.f;

#pragma unroll
    for (int r = 0; r < 8; r++) {
        float hv = row[lane + 32 * r];
#pragma unroll
        for (int o = 0; o < 12; o++) acc[o] += hv * sw[o][lane + 32 * r];
    }

#pragma unroll
    for (int o = 0; o < 12; o++) {
#pragma unroll
        for (int d = 16; d > 0; d >>= 1)
            acc[o] += __shfl_xor_sync(0xffffffffu, acc[o], d);
        acc[o] += sb[o];
    }

    float m = acc[0];
#pragma unroll
    for (int o = 1; o < 12; o++) m = fmaxf(m, acc[o]);
    float s = 0.f;
#pragma unroll
    for (int o = 0; o < 12; o++) s += expf(acc[o] - m);
    float lse = m + logf(s);

    if (lane < 12) out[(size_t)node * 12 + lane] = acc[lane] - lse;
}

// ---------------------------------------------------------------------------
// Launch
// ---------------------------------------------------------------------------
extern "C" void kernel_launch(void* const* d_in, const int* in_sizes, int n_in,
                              void* d_out, int out_size)
{
    const float* x      = (const float*)d_in[0];
    const int*   idxw   = (const int*)d_in[1];
    const float* fc0_w  = (const float*)d_in[2];
    const float* fc0_b  = (const float*)d_in[3];
    const float* w1     = (const float*)d_in[4];
    const float* b1     = (const float*)d_in[5];
    const float* w2     = (const float*)d_in[6];
    const float* b2     = (const float*)d_in[7];
    const float* w3     = (const float*)d_in[8];
    const float* b3     = (const float*)d_in[9];
    const float* fc1_w  = (const float*)d_in[10];
    const float* fc1_b  = (const float*)d_in[11];
    const float* fc2_w  = (const float*)d_in[12];
    const float* fc2_b  = (const float*)d_in[13];
    float* out = (float*)d_out;

    __half *h0, *h1, *h2, *h3;
    float* h4;
    cudaGetSymbolAddress((void**)&h0, g_h0);
    cudaGetSymbolAddress((void**)&h1, g_h1);
    cudaGetSymbolAddress((void**)&h2, g_h2);
    cudaGetSymbolAddress((void**)&h3, g_h3);
    cudaGetSymbolAddress((void**)&h4, g_h4);

    __half *gw1, *gw2, *gw3, *gf1;
    cudaGetSymbolAddress((void**)&gw1, g_w1);
    cudaGetSymbolAddress((void**)&gw2, g_w2);
    cudaGetSymbolAddress((void**)&gw3, g_w3);
    cudaGetSymbolAddress((void**)&gf1, g_f1);

    // dynamic smem: 2 * (32K A + OT*128 B) + 16K idx
    const int SM_L1  = 2 * (32768 + 32 * 128) + 16384;     //  90112
    const int SM_L2  = 2 * (32768 + 64 * 128) + 16384;     //  98304
    const int SM_L3  = 2 * (32768 + 128 * 128) + 16384;    // 114688
    const int SM_FC1 = SM_L3;

    static int attr_set = 0;
    if (!attr_set) {
        cudaFuncSetAttribute(mma_gemm_kernel<256, 32, 32, 16, true>,
                             cudaFuncAttributeMaxDynamicSharedMemorySize, SM_L1);
        cudaFuncSetAttribute(mma_gemm_kernel<512, 64, 64, 32, true>,
                             cudaFuncAttributeMaxDynamicSharedMemorySize, SM_L2);
        cudaFuncSetAttribute(mma_gemm_kernel<1024, 128, 128, 64, true>,
                             cudaFuncAttributeMaxDynamicSharedMemorySize, SM_L3);
        cudaFuncSetAttribute(mma_gemm_kernel<128, 256, 128, 0, false>,
                             cudaFuncAttributeMaxDynamicSharedMemorySize, SM_FC1);
        attr_set = 1;
    }

    const int NB = (N_NODES + 255) / 256;   // BM = 256

    detect_idx_kernel<<<1, 32>>>(idxw);
    conv_idx_kernel<<<(N_NODES * SEQ + 255) / 256, 256>>>(idxw);
    conv_w_kernel<<<(204800 + 255) / 256, 256>>>(w1, w2, w3, fc1_w);
    fc0_kernel<<<(N_NODES + 255) / 256, 256>>>(x, fc0_w, fc0_b);

    // spiral conv 1: C=16, K=256, O=32
    mma_gemm_kernel<256, 32, 32, 16, true><<<dim3(NB, 1), 512, SM_L1>>>(
        h0, gw1, b1, nullptr, h1);
    // spiral conv 2: C=32, K=512, O=64
    mma_gemm_kernel<512, 64, 64, 32, true><<<dim3(NB, 1), 512, SM_L2>>>(
        h1, gw2, b2, nullptr, h2);
    // spiral conv 3: C=64, K=1024, O=128
    mma_gemm_kernel<1024, 128, 128, 64, true><<<dim3(NB, 1), 512, SM_L3>>>(
        h2, gw3, b3, nullptr, h3);
    // fc1 dense: K=128, O=256 (2 output tiles)
    mma_gemm_kernel<128, 256, 128, 0, false><<<dim3(NB, 2), 512, SM_FC1>>>(
        h3, gf1, fc1_b, h4, nullptr);
    // fc2 + log_softmax
    fc2_lsm_kernel<<<(N_NODES + 7) / 8, 256>>>(fc2_w, fc2_b, out);
}

// round 12
// speedup vs baseline: 4.6243x; 1.0056x over previous
#include <cuda_runtime.h>
#include <cuda_fp16.h>
#include <math.h>
#include <stdint.h>

#define N_NODES 100000
#define SEQ 16

// Scratch activations as fp16 (device globals: no allocation).
__device__ __align__(16) __half g_h0[N_NODES * 16];
__device__ __align__(16) __half g_h1[N_NODES * 32];
__device__ __align__(16) __half g_h2[N_NODES * 64];
__device__ __align__(16) __half g_h3[N_NODES * 128];
__device__ __align__(16) __half g_h4[N_NODES * 256];
__device__ int g_idx[N_NODES * SEQ];
__device__ int g_is64;
// weights as fp16 (prepared once per launch)
__device__ __align__(16) __half g_w1[32 * 256];
__device__ __align__(16) __half g_w2[64 * 512];
__device__ __align__(16) __half g_w3[128 * 1024];
__device__ __align__(16) __half g_f1[256 * 128];

__device__ __forceinline__ float elu(float v) {
    return v > 0.f ? v : expm1f(v);
}

// ---------------- helpers ----------------
__device__ __forceinline__ uint32_t smem_to_u32(const void* p) {
    uint32_t a;
    asm("{ .reg .u64 tmp; cvta.to.shared.u64 tmp, %1; cvt.u32.u64 %0, tmp; }"
        : "=r"(a) : "l"(p));
    return a;
}
#define SWZ(b) ((b) ^ (((b) >> 3) & 0x70))

__device__ __forceinline__ void ldsm_x4(uint32_t* r, uint32_t addr) {
    asm volatile(
        "ldmatrix.sync.aligned.m8n8.x4.shared.b16 {%0,%1,%2,%3}, [%4];"
        : "=r"(r[0]), "=r"(r[1]), "=r"(r[2]), "=r"(r[3]) : "r"(addr));
}
__device__ __forceinline__ void mma_f16(float* c, const uint32_t* a,
                                        uint32_t b0, uint32_t b1) {
    asm volatile(
        "mma.sync.aligned.m16n8k16.row.col.f32.f16.f16.f32 "
        "{%0,%1,%2,%3}, {%4,%5,%6,%7}, {%8,%9}, {%0,%1,%2,%3};"
        : "+f"(c[0]), "+f"(c[1]), "+f"(c[2]), "+f"(c[3])
        : "r"(a[0]), "r"(a[1]), "r"(a[2]), "r"(a[3]), "r"(b0), "r"(b1));
}
__device__ __forceinline__ void cp16(uint32_t dst, const void* src) {
    asm volatile("cp.async.ca.shared.global [%0], [%1], 16;"
                 :: "r"(dst), "l"(src));
}
#define CP_COMMIT() asm volatile("cp.async.commit_group;" ::: "memory")
#define CP_WAIT0()  asm volatile("cp.async.wait_group 0;" ::: "memory")
#define CP_WAIT1()  asm volatile("cp.async.wait_group 1;" ::: "memory")

__device__ __forceinline__ uint32_t packh2(float a, float b) {
    __half2 h = __floats2half2_rn(a, b);
    return *reinterpret_cast<uint32_t*>(&h);
}

// ---------------------------------------------------------------------------
// Index dtype detection + conversion (reference declares int64; JAX default
// x64-off actually yields int32 — detect on device, clamp for safety).
// ---------------------------------------------------------------------------
__global__ void detect_idx_kernel(const int* __restrict__ w32) {
    if (threadIdx.x == 0) {
        int all_zero = 1;
        for (int k = 0; k < 64; k++) {
            if (w32[2 * k * 1024 + 1] != 0) { all_zero = 0; break; }
        }
        g_is64 = all_zero;
    }
}
__global__ void conv_idx_kernel(const int* __restrict__ w32) {
    int i = blockIdx.x * blockDim.x + threadIdx.x;
    if (i >= N_NODES * SEQ) return;
    int v = g_is64 ? w32[2 * i] : w32[i];
    if (v < 0) v = 0;
    if (v >= N_NODES) v = N_NODES - 1;
    g_idx[i] = v;
}

// ---------------------------------------------------------------------------
// All four weight conversions (fp32 -> fp16) in one kernel.
// ---------------------------------------------------------------------------
__global__ void conv_w_kernel(const float* __restrict__ w1,
                              const float* __restrict__ w2,
                              const float* __restrict__ w3,
                              const float* __restrict__ f1) {
    int i = blockIdx.x * blockDim.x + threadIdx.x;
    const float* src;
    __half* dst;
    int off;
    if (i < 8192)              { src = w1; dst = g_w1; off = i; }
    else if (i < 8192 + 32768) { src = w2; dst = g_w2; off = i - 8192; }
    else if (i < 8192 + 32768 + 131072) {
        src = w3; dst = g_w3; off = i - 8192 - 32768;
    } else if (i < 8192 + 32768 + 131072 + 32768) {
        src = f1; dst = g_f1; off = i - 8192 - 32768 - 131072;
    } else return;
    dst[off] = __float2half_rn(src[off]);
}

// ---------------------------------------------------------------------------
// fc0: [N,3] @ [3,16]^T + b, ELU -> fp16 output.
// ---------------------------------------------------------------------------
__global__ __launch_bounds__(256) void fc0_kernel(
    const float* __restrict__ x,
    const float* __restrict__ w,
    const float* __restrict__ bias)
{
    __shared__ float sw[48];
    __shared__ float sb[16];
    if (threadIdx.x < 48) sw[threadIdx.x] = w[threadIdx.x];
    if (threadIdx.x < 16) sb[threadIdx.x] = bias[threadIdx.x];
    __syncthreads();

    int n = blockIdx.x * blockDim.x + threadIdx.x;
    if (n >= N_NODES) return;

    float x0 = x[n * 3 + 0], x1 = x[n * 3 + 1], x2 = x[n * 3 + 2];
    uint32_t h[8];
#pragma unroll
    for (int j = 0; j < 8; j++) {
        float v0 = sb[2 * j] + sw[(2 * j) * 3] * x0 + sw[(2 * j) * 3 + 1] * x1 +
                   sw[(2 * j) * 3 + 2] * x2;
        float v1 = sb[2 * j + 1] + sw[(2 * j + 1) * 3] * x0 +
                   sw[(2 * j + 1) * 3 + 1] * x1 + sw[(2 * j + 1) * 3 + 2] * x2;
        h[j] = packh2(elu(v0), elu(v1));
    }
    uint4* dh = reinterpret_cast<uint4*>(g_h0 + (size_t)n * 16);
    dh[0] = make_uint4(h[0], h[1], h[2], h[3]);
    dh[1] = make_uint4(h[4], h[5], h[6], h[7]);
}

// ---------------------------------------------------------------------------
// Warp-MMA gathered GEMM: fp16 x fp16, fp32 accum, single term.
// BM=256 nodes x OT outputs per block, 512 threads (16 warps as 8x2,
// warp tile 32 x WN). BK=64 fp16 k-slab; cp.async 16B gather-copy into
// swizzled smem, 3-stage ring buffer (wait_group 1), one __syncthreads
// per slab. C: input channels per neighbor (0 = dense).
// ---------------------------------------------------------------------------
template <int K, int OTOT, int OT, int C, bool SPLIT>
__global__ __launch_bounds__(512, 1) void mma_gemm_kernel(
    const __half* __restrict__ pa,
    const __half* __restrict__ wg,
    const float* __restrict__ bias,
    float* __restrict__ outf,
    __half* __restrict__ oh)
{
    constexpr int BM     = 256;
    constexpr int NSLAB  = K / 64;
    constexpr int WN     = OT / 2;
    constexpr int NT     = WN / 8;
    constexpr int NT2    = WN / 16;
    constexpr int ACH    = BM * 8 / 512;            // A 16B chunks / thread
    constexpr int BTOT   = OT * 8;                  // B 16B chunks total
    constexpr int BCH    = (BTOT + 511) / 512;      // ceil-div
    constexpr uint32_t ABYTES = BM * 128;           // 32 KB
    constexpr uint32_t BBYTES = OT * 128;
    constexpr uint32_t BUF    = ABYTES + BBYTES;
    constexpr int NBUF   = 3;

    extern __shared__ char smem[];
    const uint32_t sbu = smem_to_u32(smem);
    int* sIdx = reinterpret_cast<int*>(smem + NBUF * BUF);

    const int t    = threadIdx.x;
    const int wid  = t >> 5;
    const int lane = t & 31;
    const int wm   = wid & 7;        // 8 warps along M
    const int wn   = wid >> 3;       // 2 warps along N
    const int gid  = lane >> 2;
    const int tid  = lane & 3;
    const int n0   = blockIdx.x * BM;
    const int o_off = blockIdx.y * OT;

    if constexpr (C > 0) {
        for (int i = t; i < BM * SEQ; i += 512) {
            int node = n0 + (i >> 4);
            if (node > N_NODES - 1) node = N_NODES - 1;
            sIdx[i] = g_idx[node * SEQ + (i & 15)];
        }
        __syncthreads();
    }

    auto issue_copy = [&](int s, int buf) {
        uint32_t base = sbu + buf * BUF;
#pragma unroll
        for (int j = 0; j < ACH; j++) {
            int id  = t + 512 * j;
            int row = id >> 3;
            int c   = id & 7;
            int kg  = s * 64 + c * 8;
            const __half* src;
            if constexpr (C == 0) {
                int node = n0 + row;
                if (node > N_NODES - 1) node = N_NODES - 1;
                src = pa + (size_t)node * K + kg;
            } else {
                int sn = sIdx[row * SEQ + kg / C];
                src = pa + (size_t)sn * C + (kg % C);
            }
            uint32_t dst = base + SWZ((uint32_t)(row * 128 + c * 16));
            cp16(dst, src);
        }
#pragma unroll
        for (int j = 0; j < BCH; j++) {
            int id = t + 512 * j;
            if (id < BTOT) {
                int o = id >> 3;
                int c = id & 7;
                const __half* src =
                    wg + (size_t)(o_off + o) * K + s * 64 + c * 8;
                uint32_t dst = base + ABYTES +
                               SWZ((uint32_t)(o * 128 + c * 16));
                cp16(dst, src);
            }
        }
        CP_COMMIT();
    };

    float acc[2][NT][4];
#pragma unroll
    for (int m = 0; m < 2; m++)
#pragma unroll
        for (int n = 0; n < NT; n++)
#pragma unroll
            for (int q = 0; q < 4; q++) acc[m][n][q] = 0.f;

    // prologue: fill up to 2 slabs ahead
    issue_copy(0, 0);
    if (NSLAB > 1) issue_copy(1, 1);
    if (NSLAB > 1) CP_WAIT1(); else CP_WAIT0();   // slab 0 resident
    __syncthreads();

    const uint32_t flrow  = lane & 15;
    const uint32_t fchalf = (lane >> 4) * 16;

    for (int s = 0; s < NSLAB; s++) {
        const int buf = s % NBUF;
        if (s + 2 < NSLAB) issue_copy(s + 2, (s + 2) % NBUF);

        uint32_t base = sbu + buf * BUF;
#pragma unroll
        for (int kc = 0; kc < 4; kc++) {
            uint32_t colb = kc * 32 + fchalf;
            uint32_t ah[2][4];
#pragma unroll
            for (int mt = 0; mt < 2; mt++) {
                uint32_t off = (wm * 32 + mt * 16 + flrow) * 128 + colb;
                ldsm_x4(ah[mt], base + SWZ(off));
            }
#pragma unroll
            for (int n2 = 0; n2 < NT2; n2++) {
                uint32_t off = (wn * WN + n2 * 16 + flrow) * 128 + colb;
                uint32_t sw  = SWZ(off);
                uint32_t fh[4];
                ldsm_x4(fh, base + ABYTES + sw);
#pragma unroll
                for (int mt = 0; mt < 2; mt++) {
                    mma_f16(acc[mt][n2 * 2],     ah[mt], fh[0], fh[2]);
                    mma_f16(acc[mt][n2 * 2 + 1], ah[mt], fh[1], fh[3]);
                }
            }
        }

        if (s + 1 < NSLAB) {
            if (s + 2 < NSLAB) CP_WAIT1(); else CP_WAIT0();  // slab s+1 done
            __syncthreads();
        }
    }

    // ---- epilogue: bias + ELU; fp32 or fp16 output ----
#pragma unroll
    for (int mt = 0; mt < 2; mt++) {
#pragma unroll
        for (int nt = 0; nt < NT; nt++) {
            int col = o_off + wn * WN + nt * 8 + tid * 2;
            float b0 = bias[col], b1 = bias[col + 1];
            int r0 = n0 + wm * 32 + mt * 16 + gid;
            int r1 = r0 + 8;
            float v0 = elu(acc[mt][nt][0] + b0);
            float v1 = elu(acc[mt][nt][1] + b1);
            float v2 = elu(acc[mt][nt][2] + b0);
            float v3 = elu(acc[mt][nt][3] + b1);
            if constexpr (SPLIT) {
                if (r0 < N_NODES)
                    *reinterpret_cast<uint32_t*>(oh + (size_t)r0 * OTOT + col) =
                        packh2(v0, v1);
                if (r1 < N_NODES)
                    *reinterpret_cast<uint32_t*>(oh + (size_t)r1 * OTOT + col) =
                        packh2(v2, v3);
            } else {
                if (r0 < N_NODES) {
                    float2 v; v.x = v0; v.y = v1;
                    *reinterpret_cast<float2*>(outf + (size_t)r0 * OTOT + col) = v;
                }
                if (r1 < N_NODES) {
                    float2 v; v.x = v2; v.y = v3;
                    *reinterpret_cast<float2*>(outf + (size_t)r1 * OTOT + col) = v;
                }
            }
        }
    }
}

// ---------------------------------------------------------------------------
// fc2 + log_softmax: one warp per node. 12 outputs from 256 fp16 inputs.
// ---------------------------------------------------------------------------
__global__ __launch_bounds__(256) void fc2_lsm_kernel(
    const float* __restrict__ w,
    const float* __restrict__ bias,
    float* __restrict__ out)
{
    __shared__ float sw[12][256];
    __shared__ float sb[12];
    int t = threadIdx.x;
    for (int i = t; i < 12 * 256; i += 256) sw[i >> 8][i & 255] = w[i];
    if (t < 12) sb[t] = bias[t];
    __syncthreads();

    int node = blockIdx.x * 8 + (t >> 5);
    int lane = t & 31;
    if (node >= N_NODES) return;

    const __half* row = g_h4 + (size_t)node * 256;
    float acc[12];
#pragma unroll
    for (int o = 0; o < 12; o++) acc[o] = 0.f;

#pragma unroll
    for (int r = 0; r < 8; r++) {
        float hv = __half2float(row[lane + 32 * r]);
#pragma unroll
        for (int o = 0; o < 12; o++) acc[o] += hv * sw[o][lane + 32 * r];
    }

#pragma unroll
    for (int o = 0; o < 12; o++) {
#pragma unroll
        for (int d = 16; d > 0; d >>= 1)
            acc[o] += __shfl_xor_sync(0xffffffffu, acc[o], d);
        acc[o] += sb[o];
    }

    float m = acc[0];
#pragma unroll
    for (int o = 1; o < 12; o++) m = fmaxf(m, acc[o]);
    float s = 0.f;
#pragma unroll
    for (int o = 0; o < 12; o++) s += expf(acc[o] - m);
    float lse = m + logf(s);

    if (lane < 12) out[(size_t)node * 12 + lane] = acc[lane] - lse;
}

// ---------------------------------------------------------------------------
// Launch
// ---------------------------------------------------------------------------
extern "C" void kernel_launch(void* const* d_in, const int* in_sizes, int n_in,
                              void* d_out, int out_size)
{
    const float* x      = (const float*)d_in[0];
    const int*   idxw   = (const int*)d_in[1];
    const float* fc0_w  = (const float*)d_in[2];
    const float* fc0_b  = (const float*)d_in[3];
    const float* w1     = (const float*)d_in[4];
    const float* b1     = (const float*)d_in[5];
    const float* w2     = (const float*)d_in[6];
    const float* b2     = (const float*)d_in[7];
    const float* w3     = (const float*)d_in[8];
    const float* b3     = (const float*)d_in[9];
    const float* fc1_w  = (const float*)d_in[10];
    const float* fc1_b  = (const float*)d_in[11];
    const float* fc2_w  = (const float*)d_in[12];
    const float* fc2_b  = (const float*)d_in[13];
    float* out = (float*)d_out;

    __half *h0, *h1, *h2, *h3, *h4;
    cudaGetSymbolAddress((void**)&h0, g_h0);
    cudaGetSymbolAddress((void**)&h1, g_h1);
    cudaGetSymbolAddress((void**)&h2, g_h2);
    cudaGetSymbolAddress((void**)&h3, g_h3);
    cudaGetSymbolAddress((void**)&h4, g_h4);

    __half *gw1, *gw2, *gw3, *gf1;
    cudaGetSymbolAddress((void**)&gw1, g_w1);
    cudaGetSymbolAddress((void**)&gw2, g_w2);
    cudaGetSymbolAddress((void**)&gw3, g_w3);
    cudaGetSymbolAddress((void**)&gf1, g_f1);

    // dynamic smem: 3 * (32K A + OT*128 B) + 16K idx
    const int SM_L1  = 3 * (32768 + 32 * 128) + 16384;     // 126976
    const int SM_L2  = 3 * (32768 + 64 * 128) + 16384;     // 139264
    const int SM_L3  = 3 * (32768 + 128 * 128) + 16384;    // 163840
    const int SM_FC1 = SM_L3;

    static int attr_set = 0;
    if (!attr_set) {
        cudaFuncSetAttribute(mma_gemm_kernel<256, 32, 32, 16, true>,
                             cudaFuncAttributeMaxDynamicSharedMemorySize, SM_L1);
        cudaFuncSetAttribute(mma_gemm_kernel<512, 64, 64, 32, true>,
                             cudaFuncAttributeMaxDynamicSharedMemorySize, SM_L2);
        cudaFuncSetAttribute(mma_gemm_kernel<1024, 128, 128, 64, true>,
                             cudaFuncAttributeMaxDynamicSharedMemorySize, SM_L3);
        cudaFuncSetAttribute(mma_gemm_kernel<128, 256, 128, 0, true>,
                             cudaFuncAttributeMaxDynamicSharedMemorySize, SM_FC1);
        attr_set = 1;
    }

    const int NB = (N_NODES + 255) / 256;   // BM = 256

    detect_idx_kernel<<<1, 32>>>(idxw);
    conv_idx_kernel<<<(N_NODES * SEQ + 255) / 256, 256>>>(idxw);
    conv_w_kernel<<<(204800 + 255) / 256, 256>>>(w1, w2, w3, fc1_w);
    fc0_kernel<<<(N_NODES + 255) / 256, 256>>>(x, fc0_w, fc0_b);

    // spiral conv 1: C=16, K=256, O=32
    mma_gemm_kernel<256, 32, 32, 16, true><<<dim3(NB, 1), 512, SM_L1>>>(
        h0, gw1, b1, nullptr, h1);
    // spiral conv 2: C=32, K=512, O=64
    mma_gemm_kernel<512, 64, 64, 32, true><<<dim3(NB, 1), 512, SM_L2>>>(
        h1, gw2, b2, nullptr, h2);
    // spiral conv 3: C=64, K=1024, O=128
    mma_gemm_kernel<1024, 128, 128, 64, true><<<dim3(NB, 1), 512, SM_L3>>>(
        h2, gw3, b3, nullptr, h3);
    // fc1 dense: K=128, O=256 (2 output tiles), fp16 output
    mma_gemm_kernel<128, 256, 128, 0, true><<<dim3(NB, 2), 512, SM_FC1>>>(
        h3, gf1, fc1_b, nullptr, h4);
    // fc2 + log_softmax
    fc2_lsm_kernel<<<(N_NODES + 7) / 8, 256>>>(fc2_w, fc2_b, out);
}

// round 13
// speedup vs baseline: 4.8444x; 1.0476x over previous
#include <cuda_runtime.h>
#include <cuda_fp16.h>
#include <math.h>
#include <stdint.h>

#define N_NODES 100000
#define SEQ 16

// Scratch activations as fp16 (device globals: no allocation).
__device__ __align__(16) __half g_h0[N_NODES * 16];
__device__ __align__(16) __half g_h1[N_NODES * 32];
__device__ __align__(16) __half g_h2[N_NODES * 64];
__device__ __align__(16) __half g_h3[N_NODES * 128];
__device__ __align__(16) __half g_h4[N_NODES * 256];
__device__ int g_idx[N_NODES * SEQ];
__device__ int g_is64;
// weights as fp16 (prepared once per launch)
__device__ __align__(16) __half g_w1[32 * 256];
__device__ __align__(16) __half g_w2[64 * 512];
__device__ __align__(16) __half g_w3[128 * 1024];
__device__ __align__(16) __half g_f1[256 * 128];

__device__ __forceinline__ float elu(float v) {
    return v > 0.f ? v : expm1f(v);
}

// ---------------- helpers ----------------
__device__ __forceinline__ uint32_t smem_to_u32(const void* p) {
    uint32_t a;
    asm("{ .reg .u64 tmp; cvta.to.shared.u64 tmp, %1; cvt.u32.u64 %0, tmp; }"
        : "=r"(a) : "l"(p));
    return a;
}
#define SWZ(b) ((b) ^ (((b) >> 3) & 0x70))

__device__ __forceinline__ void ldsm_x4(uint32_t* r, uint32_t addr) {
    asm volatile(
        "ldmatrix.sync.aligned.m8n8.x4.shared.b16 {%0,%1,%2,%3}, [%4];"
        : "=r"(r[0]), "=r"(r[1]), "=r"(r[2]), "=r"(r[3]) : "r"(addr));
}
__device__ __forceinline__ void mma_f16(float* c, const uint32_t* a,
                                        uint32_t b0, uint32_t b1) {
    asm volatile(
        "mma.sync.aligned.m16n8k16.row.col.f32.f16.f16.f32 "
        "{%0,%1,%2,%3}, {%4,%5,%6,%7}, {%8,%9}, {%0,%1,%2,%3};"
        : "+f"(c[0]), "+f"(c[1]), "+f"(c[2]), "+f"(c[3])
        : "r"(a[0]), "r"(a[1]), "r"(a[2]), "r"(a[3]), "r"(b0), "r"(b1));
}
__device__ __forceinline__ void cp16(uint32_t dst, const void* src) {
    asm volatile("cp.async.ca.shared.global [%0], [%1], 16;"
                 :: "r"(dst), "l"(src));
}
#define CP_COMMIT() asm volatile("cp.async.commit_group;" ::: "memory")
#define CP_WAIT0()  asm volatile("cp.async.wait_group 0;" ::: "memory")
#define CP_WAIT1()  asm volatile("cp.async.wait_group 1;" ::: "memory")

__device__ __forceinline__ uint32_t packh2(float a, float b) {
    __half2 h = __floats2half2_rn(a, b);
    return *reinterpret_cast<uint32_t*>(&h);
}

// ---------------------------------------------------------------------------
// Index dtype detection + conversion (reference declares int64; JAX default
// x64-off actually yields int32 — detect on device, clamp for safety).
// ---------------------------------------------------------------------------
__global__ void detect_idx_kernel(const int* __restrict__ w32) {
    if (threadIdx.x == 0) {
        int all_zero = 1;
        for (int k = 0; k < 64; k++) {
            if (w32[2 * k * 1024 + 1] != 0) { all_zero = 0; break; }
        }
        g_is64 = all_zero;
    }
}
__global__ void conv_idx_kernel(const int* __restrict__ w32) {
    int i = blockIdx.x * blockDim.x + threadIdx.x;
    if (i >= N_NODES * SEQ) return;
    int v = g_is64 ? w32[2 * i] : w32[i];
    if (v < 0) v = 0;
    if (v >= N_NODES) v = N_NODES - 1;
    g_idx[i] = v;
}

// ---------------------------------------------------------------------------
// Fused prep: blocks [0,800) convert all weights fp32->fp16;
// blocks [800, 800+391) run fc0 (so the next launch, L1 mma, is the one
// ncu captures).
// ---------------------------------------------------------------------------
__global__ __launch_bounds__(256) void prep_kernel(
    const float* __restrict__ w1, const float* __restrict__ w2,
    const float* __restrict__ w3, const float* __restrict__ f1,
    const float* __restrict__ x,
    const float* __restrict__ fc0_w, const float* __restrict__ fc0_b)
{
    if (blockIdx.x < 800) {
        int i = blockIdx.x * 256 + threadIdx.x;   // 0 .. 204799
        const float* src;
        __half* dst;
        int off;
        if (i < 8192)              { src = w1; dst = g_w1; off = i; }
        else if (i < 40960)        { src = w2; dst = g_w2; off = i - 8192; }
        else if (i < 172032)       { src = w3; dst = g_w3; off = i - 40960; }
        else                       { src = f1; dst = g_f1; off = i - 172032; }
        dst[off] = __float2half_rn(src[off]);
        return;
    }

    // fc0 part
    __shared__ float sw[48];
    __shared__ float sb[16];
    if (threadIdx.x < 48) sw[threadIdx.x] = fc0_w[threadIdx.x];
    if (threadIdx.x < 16) sb[threadIdx.x] = fc0_b[threadIdx.x];
    __syncthreads();

    int n = (blockIdx.x - 800) * 256 + threadIdx.x;
    if (n >= N_NODES) return;

    float x0 = x[n * 3 + 0], x1 = x[n * 3 + 1], x2 = x[n * 3 + 2];
    uint32_t h[8];
#pragma unroll
    for (int j = 0; j < 8; j++) {
        float v0 = sb[2 * j] + sw[(2 * j) * 3] * x0 + sw[(2 * j) * 3 + 1] * x1 +
                   sw[(2 * j) * 3 + 2] * x2;
        float v1 = sb[2 * j + 1] + sw[(2 * j + 1) * 3] * x0 +
                   sw[(2 * j + 1) * 3 + 1] * x1 + sw[(2 * j + 1) * 3 + 2] * x2;
        h[j] = packh2(elu(v0), elu(v1));
    }
    uint4* dh = reinterpret_cast<uint4*>(g_h0 + (size_t)n * 16);
    dh[0] = make_uint4(h[0], h[1], h[2], h[3]);
    dh[1] = make_uint4(h[4], h[5], h[6], h[7]);
}

// ---------------------------------------------------------------------------
// Warp-MMA gathered GEMM: fp16 x fp16, fp32 accum, single term.
// BM=128 nodes x OT outputs per block, 256 threads (8 warps as 4x2,
// warp tile 32 x WN). BK=64 fp16 k-slab; cp.async 16B gather-copy into
// swizzled smem, 3-stage ring (one __syncthreads per slab). smem <= 106KB
// -> 2 blocks/SM so barrier drains in one block overlap the other block's
// compute. C: input channels per neighbor (0 = dense).
// ---------------------------------------------------------------------------
template <int K, int OTOT, int OT, int C, bool SPLIT>
__global__ __launch_bounds__(256, 2) void mma_gemm_kernel(
    const __half* __restrict__ pa,
    const __half* __restrict__ wg,
    const float* __restrict__ bias,
    float* __restrict__ outf,
    __half* __restrict__ oh)
{
    constexpr int BM     = 128;
    constexpr int THREADS = 256;
    constexpr int NSLAB  = K / 64;
    constexpr int WN     = OT / 2;
    constexpr int NT     = WN / 8;
    constexpr int NT2    = WN / 16;
    constexpr int ACH    = BM * 8 / THREADS;        // A 16B chunks / thread
    constexpr int BTOT   = OT * 8;                  // B 16B chunks total
    constexpr int BCH    = (BTOT + THREADS - 1) / THREADS;
    constexpr uint32_t ABYTES = BM * 128;           // 16 KB
    constexpr uint32_t BBYTES = OT * 128;
    constexpr uint32_t BUF    = ABYTES + BBYTES;
    constexpr int NBUF   = 3;

    extern __shared__ char smem[];
    const uint32_t sbu = smem_to_u32(smem);
    int* sIdx = reinterpret_cast<int*>(smem + NBUF * BUF);

    const int t    = threadIdx.x;
    const int wid  = t >> 5;
    const int lane = t & 31;
    const int wm   = wid & 3;        // 4 warps along M
    const int wn   = wid >> 2;       // 2 warps along N
    const int gid  = lane >> 2;
    const int tid  = lane & 3;
    const int n0   = blockIdx.x * BM;
    const int o_off = blockIdx.y * OT;

    if constexpr (C > 0) {
        for (int i = t; i < BM * SEQ; i += THREADS) {
            int node = n0 + (i >> 4);
            if (node > N_NODES - 1) node = N_NODES - 1;
            sIdx[i] = g_idx[node * SEQ + (i & 15)];
        }
        __syncthreads();
    }

    auto issue_copy = [&](int s, int buf) {
        uint32_t base = sbu + buf * BUF;
#pragma unroll
        for (int j = 0; j < ACH; j++) {
            int id  = t + THREADS * j;
            int row = id >> 3;
            int c   = id & 7;
            int kg  = s * 64 + c * 8;
            const __half* src;
            if constexpr (C == 0) {
                int node = n0 + row;
                if (node > N_NODES - 1) node = N_NODES - 1;
                src = pa + (size_t)node * K + kg;
            } else {
                int sn = sIdx[row * SEQ + kg / C];
                src = pa + (size_t)sn * C + (kg % C);
            }
            uint32_t dst = base + SWZ((uint32_t)(row * 128 + c * 16));
            cp16(dst, src);
        }
#pragma unroll
        for (int j = 0; j < BCH; j++) {
            int id = t + THREADS * j;
            if (id < BTOT) {
                int o = id >> 3;
                int c = id & 7;
                const __half* src =
                    wg + (size_t)(o_off + o) * K + s * 64 + c * 8;
                uint32_t dst = base + ABYTES +
                               SWZ((uint32_t)(o * 128 + c * 16));
                cp16(dst, src);
            }
        }
        CP_COMMIT();
    };

    float acc[2][NT][4];
#pragma unroll
    for (int m = 0; m < 2; m++)
#pragma unroll
        for (int n = 0; n < NT; n++)
#pragma unroll
            for (int q = 0; q < 4; q++) acc[m][n][q] = 0.f;

    // prologue: fill up to 2 slabs ahead
    issue_copy(0, 0);
    if (NSLAB > 1) issue_copy(1, 1);
    if (NSLAB > 1) CP_WAIT1(); else CP_WAIT0();   // slab 0 resident
    __syncthreads();

    const uint32_t flrow  = lane & 15;
    const uint32_t fchalf = (lane >> 4) * 16;

    for (int s = 0; s < NSLAB; s++) {
        const int buf = s % NBUF;
        if (s + 2 < NSLAB) issue_copy(s + 2, (s + 2) % NBUF);

        uint32_t base = sbu + buf * BUF;
#pragma unroll
        for (int kc = 0; kc < 4; kc++) {
            uint32_t colb = kc * 32 + fchalf;
            uint32_t ah[2][4];
#pragma unroll
            for (int mt = 0; mt < 2; mt++) {
                uint32_t off = (wm * 32 + mt * 16 + flrow) * 128 + colb;
                ldsm_x4(ah[mt], base + SWZ(off));
            }
#pragma unroll
            for (int n2 = 0; n2 < NT2; n2++) {
                uint32_t off = (wn * WN + n2 * 16 + flrow) * 128 + colb;
                uint32_t sw  = SWZ(off);
                uint32_t fh[4];
                ldsm_x4(fh, base + ABYTES + sw);
#pragma unroll
                for (int mt = 0; mt < 2; mt++) {
                    mma_f16(acc[mt][n2 * 2],     ah[mt], fh[0], fh[2]);
                    mma_f16(acc[mt][n2 * 2 + 1], ah[mt], fh[1], fh[3]);
                }
            }
        }

        if (s + 1 < NSLAB) {
            if (s + 2 < NSLAB) CP_WAIT1(); else CP_WAIT0();  // slab s+1 done
            __syncthreads();
        }
    }

    // ---- epilogue: bias + ELU; fp32 or fp16 output ----
#pragma unroll
    for (int mt = 0; mt < 2; mt++) {
#pragma unroll
        for (int nt = 0; nt < NT; nt++) {
            int col = o_off + wn * WN + nt * 8 + tid * 2;
            float b0 = bias[col], b1 = bias[col + 1];
            int r0 = n0 + wm * 32 + mt * 16 + gid;
            int r1 = r0 + 8;
            float v0 = elu(acc[mt][nt][0] + b0);
            float v1 = elu(acc[mt][nt][1] + b1);
            float v2 = elu(acc[mt][nt][2] + b0);
            float v3 = elu(acc[mt][nt][3] + b1);
            if constexpr (SPLIT) {
                if (r0 < N_NODES)
                    *reinterpret_cast<uint32_t*>(oh + (size_t)r0 * OTOT + col) =
                        packh2(v0, v1);
                if (r1 < N_NODES)
                    *reinterpret_cast<uint32_t*>(oh + (size_t)r1 * OTOT + col) =
                        packh2(v2, v3);
            } else {
                if (r0 < N_NODES) {
                    float2 v; v.x = v0; v.y = v1;
                    *reinterpret_cast<float2*>(outf + (size_t)r0 * OTOT + col) = v;
                }
                if (r1 < N_NODES) {
                    float2 v; v.x = v2; v.y = v3;
                    *reinterpret_cast<float2*>(outf + (size_t)r1 * OTOT + col) = v;
                }
            }
        }
    }
}

// ---------------------------------------------------------------------------
// fc2 + log_softmax: one warp per node. 12 outputs from 256 fp16 inputs.
// half2-vectorized row loads.
// ---------------------------------------------------------------------------
__global__ __launch_bounds__(256) void fc2_lsm_kernel(
    const float* __restrict__ w,
    const float* __restrict__ bias,
    float* __restrict__ out)
{
    __shared__ float sw[12][256];
    __shared__ float sb[12];
    int t = threadIdx.x;
    for (int i = t; i < 12 * 256; i += 256) sw[i >> 8][i & 255] = w[i];
    if (t < 12) sb[t] = bias[t];
    __syncthreads();

    int node = blockIdx.x * 8 + (t >> 5);
    int lane = t & 31;
    if (node >= N_NODES) return;

    const __half2* row2 =
        reinterpret_cast<const __half2*>(g_h4 + (size_t)node * 256);
    float acc[12];
#pragma unroll
    for (int o = 0; o < 12; o++) acc[o] = 0.f;

#pragma unroll
    for (int r = 0; r < 4; r++) {
        float2 f = __half22float2(row2[lane + 32 * r]);
        int col = 2 * (lane + 32 * r);
#pragma unroll
        for (int o = 0; o < 12; o++)
            acc[o] += f.x * sw[o][col] + f.y * sw[o][col + 1];
    }

#pragma unroll
    for (int o = 0; o < 12; o++) {
#pragma unroll
        for (int d = 16; d > 0; d >>= 1)
            acc[o] += __shfl_xor_sync(0xffffffffu, acc[o], d);
        acc[o] += sb[o];
    }

    float m = acc[0];
#pragma unroll
    for (int o = 1; o < 12; o++) m = fmaxf(m, acc[o]);
    float s = 0.f;
#pragma unroll
    for (int o = 0; o < 12; o++) s += expf(acc[o] - m);
    float lse = m + logf(s);

    if (lane < 12) out[(size_t)node * 12 + lane] = acc[lane] - lse;
}

// ---------------------------------------------------------------------------
// Launch
// ---------------------------------------------------------------------------
extern "C" void kernel_launch(void* const* d_in, const int* in_sizes, int n_in,
                              void* d_out, int out_size)
{
    const float* x      = (const float*)d_in[0];
    const int*   idxw   = (const int*)d_in[1];
    const float* fc0_w  = (const float*)d_in[2];
    const float* fc0_b  = (const float*)d_in[3];
    const float* w1     = (const float*)d_in[4];
    const float* b1     = (const float*)d_in[5];
    const float* w2     = (const float*)d_in[6];
    const float* b2     = (const float*)d_in[7];
    const float* w3     = (const float*)d_in[8];
    const float* b3     = (const float*)d_in[9];
    const float* fc1_w  = (const float*)d_in[10];
    const float* fc1_b  = (const float*)d_in[11];
    const float* fc2_w  = (const float*)d_in[12];
    const float* fc2_b  = (const float*)d_in[13];
    float* out = (float*)d_out;

    __half *h0, *h1, *h2, *h3, *h4;
    cudaGetSymbolAddress((void**)&h0, g_h0);
    cudaGetSymbolAddress((void**)&h1, g_h1);
    cudaGetSymbolAddress((void**)&h2, g_h2);
    cudaGetSymbolAddress((void**)&h3, g_h3);
    cudaGetSymbolAddress((void**)&h4, g_h4);

    __half *gw1, *gw2, *gw3, *gf1;
    cudaGetSymbolAddress((void**)&gw1, g_w1);
    cudaGetSymbolAddress((void**)&gw2, g_w2);
    cudaGetSymbolAddress((void**)&gw3, g_w3);
    cudaGetSymbolAddress((void**)&gf1, g_f1);

    // dynamic smem: 3 * (16K A + OT*128 B) + 8K idx
    const int SM_L1  = 3 * (16384 + 32 * 128) + 8192;     //  69632
    const int SM_L2  = 3 * (16384 + 64 * 128) + 8192;     //  81920
    const int SM_L3  = 3 * (16384 + 128 * 128) + 8192;    // 106496
    const int SM_FC1 = SM_L3;

    static int attr_set = 0;
    if (!attr_set) {
        cudaFuncSetAttribute(mma_gemm_kernel<256, 32, 32, 16, true>,
                             cudaFuncAttributeMaxDynamicSharedMemorySize, SM_L1);
        cudaFuncSetAttribute(mma_gemm_kernel<512, 64, 64, 32, true>,
                             cudaFuncAttributeMaxDynamicSharedMemorySize, SM_L2);
        cudaFuncSetAttribute(mma_gemm_kernel<1024, 128, 128, 64, true>,
                             cudaFuncAttributeMaxDynamicSharedMemorySize, SM_L3);
        cudaFuncSetAttribute(mma_gemm_kernel<128, 256, 128, 0, true>,
                             cudaFuncAttributeMaxDynamicSharedMemorySize, SM_FC1);
        attr_set = 1;
    }

    const int NB = (N_NODES + 127) / 128;   // BM = 128 -> 782 blocks

    detect_idx_kernel<<<1, 32>>>(idxw);                               // 0
    conv_idx_kernel<<<(N_NODES * SEQ + 255) / 256, 256>>>(idxw);      // 1
    prep_kernel<<<800 + (N_NODES + 255) / 256, 256>>>(                // 2
        w1, w2, w3, fc1_w, x, fc0_w, fc0_b);

    // spiral conv 1: C=16, K=256, O=32                               // 3 (ncu)
    mma_gemm_kernel<256, 32, 32, 16, true><<<dim3(NB, 1), 256, SM_L1>>>(
        h0, gw1, b1, nullptr, h1);
    // spiral conv 2: C=32, K=512, O=64                               // 4
    mma_gemm_kernel<512, 64, 64, 32, true><<<dim3(NB, 1), 256, SM_L2>>>(
        h1, gw2, b2, nullptr, h2);
    // spiral conv 3: C=64, K=1024, O=128                             // 5
    mma_gemm_kernel<1024, 128, 128, 64, true><<<dim3(NB, 1), 256, SM_L3>>>(
        h2, gw3, b3, nullptr, h3);
    // fc1 dense: K=128, O=256 (2 output tiles), fp16 output          // 6
    mma_gemm_kernel<128, 256, 128, 0, true><<<dim3(NB, 2), 256, SM_FC1>>>(
        h3, gf1, fc1_b, nullptr, h4);
    // fc2 + log_softmax                                              // 7
    fc2_lsm_kernel<<<(N_NODES + 7) / 8, 256>>>(fc2_w, fc2_b, out);
}